// round 16
// baseline (speedup 1.0000x reference)
#include <cuda_runtime.h>
#include <cuda_fp16.h>
#include <cstdint>
#include <cstddef>

// ---------------------------------------------------------------------------
// Problem constants
// ---------------------------------------------------------------------------
#define E_DIM   1024
#define QKV_N   3072
#define H_DIM   16
#define D_DIM   64
#define B_DIM   2
#define T_DIM   32
#define N_DIM   256
#define MTOK    (B_DIM * T_DIM * N_DIM)   // 16384 tokens total
#define MTOK_B  (T_DIM * N_DIM)           // 8192 tokens per batch
#define KSEL    256
#define MAXLEN  512
#define RB_ONE  ((2 * MAXLEN - 1) * H_DIM)
#define OUT_ROWS 448                      // 256 + 128 + 64
#define SPLITK_SEL 8

// ---------------------------------------------------------------------------
// Scratch (device globals — no allocations allowed)
// ---------------------------------------------------------------------------
__device__ __half g_QKVh[MTOK * QKV_N];   // merged Q|K|V per token, fp16
__device__ float g_SC[MTOK * KSEL];
__device__ float g_S1[B_DIM * KSEL * E_DIM];   // wts^T @ ctx
__device__ float g_SEL[B_DIM * KSEL * E_DIM];  // final selected tokens

// fp16 activations
__device__ __half g_Ah[MTOK * E_DIM];     // attention ctx (fp16)
__device__ __half g_Ah2[MTOK * E_DIM];
__device__ __half g_Al2[MTOK * E_DIM];
// transposed fp16 weights
__device__ __half g_WqkvTh[4 * 3 * E_DIM * E_DIM];  // [a][q|k|v][N=E][K=E] hi
__device__ __half g_WqkvTl[4 * 3 * E_DIM * E_DIM];  // lo
__device__ __half g_Wd16[4 * E_DIM * E_DIM];        // wd plain (row-major) fp16
__device__ __half g_WdT3[E_DIM * E_DIM];            // wd[3] transposed fp16
__device__ __half g_WcT[3 * QKV_N * E_DIM];         // combined W'^T fp16
__device__ __half g_SWTh[KSEL * E_DIM];             // selw^T hi
__device__ __half g_SWTl[KSEL * E_DIM];             // selw^T lo
__device__ __half g_Bsel[KSEL * E_DIM];             // (Wd3 @ selw)^T fp16
// selection mma operands
__device__ __half g_SCTh[B_DIM * KSEL * MTOK_B];    // wts^T hi
__device__ __half g_SCTl[B_DIM * KSEL * MTOK_B];    // wts^T lo
__device__ __half g_CTh[B_DIM * E_DIM * MTOK_B];    // ctx^T hi
__device__ float  g_Bqkv[4 * QKV_N];
__device__ float  g_Bcomb[3 * QKV_N];
__device__ float  g_Bias2[KSEL];
__device__ float  g_Bzero[E_DIM];

// ---------------------------------------------------------------------------
// PTX helpers
// ---------------------------------------------------------------------------
__device__ __forceinline__ void cp_async16(uint32_t dst, const void* src) {
    asm volatile("cp.async.cg.shared.global [%0], [%1], 16;" :: "r"(dst), "l"(src));
}
__device__ __forceinline__ void cp_commit() {
    asm volatile("cp.async.commit_group;" ::: "memory");
}
template <int N>
__device__ __forceinline__ void cp_wait_group() {
    asm volatile("cp.async.wait_group %0;" :: "n"(N) : "memory");
}
__device__ __forceinline__ void ldmatrix_x4(uint32_t* r, uint32_t addr) {
    asm volatile("ldmatrix.sync.aligned.m8n8.x4.shared.b16 {%0,%1,%2,%3}, [%4];"
                 : "=r"(r[0]), "=r"(r[1]), "=r"(r[2]), "=r"(r[3]) : "r"(addr));
}
__device__ __forceinline__ void mma_f16(float* d, const uint32_t* a,
                                        uint32_t b0, uint32_t b1) {
    asm volatile(
        "mma.sync.aligned.m16n8k16.row.col.f32.f16.f16.f32 "
        "{%0,%1,%2,%3}, {%4,%5,%6,%7}, {%8,%9}, {%0,%1,%2,%3};"
        : "+f"(d[0]), "+f"(d[1]), "+f"(d[2]), "+f"(d[3])
        : "r"(a[0]), "r"(a[1]), "r"(a[2]), "r"(a[3]), "r"(b0), "r"(b1));
}
__device__ __forceinline__ uint32_t h2pack(float a, float b) {
    __half2 h = __floats2half2_rn(a, b);
    return *(uint32_t*)&h;
}

// ---------------------------------------------------------------------------
// fp16 GEMM via mma.sync, k-chunk 64 (tile 128x64, row stride 72).
// ---------------------------------------------------------------------------
#define GSTAGES 3
#define ROWP  72
#define TILE_B (128 * ROWP * 2)            // 18432 per tile

template <int SEGS>
__global__ __launch_bounds__(256, 2)
void gemm_f16(const __half* __restrict__ Ah, const __half* __restrict__ Al,
              const __half* __restrict__ B,
              const float* __restrict__ bias, float* __restrict__ C,
              __half* __restrict__ Ch, __half* __restrict__ Cl,
              int Nfull, int Kfull,
              size_t zA, size_t zB, size_t zC)
{
    constexpr int STB = (SEGS + 1) * TILE_B;

    extern __shared__ char smem[];
    const uint32_t sb = (uint32_t)__cvta_generic_to_shared(smem);
    const int tid = threadIdx.x;
    const int lane = tid & 31;
    const int warp = tid >> 5;
    const int wm = warp >> 1;
    const int wn = warp & 1;
    const int m0 = blockIdx.y * 128;
    const int n0 = blockIdx.x * 128;

    Ah += (size_t)blockIdx.z * zA;
    if (SEGS == 2) Al += (size_t)blockIdx.z * zA;
    B  += (size_t)blockIdx.z * zB;
    if (C)  C  += (size_t)blockIdx.z * zC;
    if (Ch) Ch += (size_t)blockIdx.z * zC;
    if (Cl) Cl += (size_t)blockIdx.z * zC;

    const int NCH = Kfull >> 6;

    float acc[2][8][4];
#pragma unroll
    for (int mi = 0; mi < 2; mi++)
#pragma unroll
        for (int ni = 0; ni < 8; ni++)
#pragma unroll
            for (int q = 0; q < 4; q++) acc[mi][ni][q] = 0.f;

    auto load_chunk = [&](int c, int stage) {
        const int kb = c << 6;
        const uint32_t base = sb + stage * STB;
#pragma unroll
        for (int j = 0; j < 4; j++) {
            const int idx = tid + j * 256;
            const int r = idx >> 3, cs = idx & 7;
            const uint32_t soff = (uint32_t)(r * ROWP + cs * 8) * 2;
            const size_t goff = (size_t)r * Kfull + kb + cs * 8;
            cp_async16(base + soff, Ah + (size_t)m0 * Kfull + goff);
            if (SEGS == 2)
                cp_async16(base + TILE_B + soff, Al + (size_t)m0 * Kfull + goff);
            cp_async16(base + SEGS * TILE_B + soff, B + (size_t)n0 * Kfull + goff);
        }
    };

#pragma unroll
    for (int s = 0; s < GSTAGES - 1; s++) {
        if (s < NCH) load_chunk(s, s);
        cp_commit();
    }

    const int la_i = lane & 7;
    const int la_g = lane >> 3;
    const int a_rowadd = la_i + ((la_g & 1) << 3);
    const int a_coladd = (la_g >> 1) << 3;
    const int b_rowadd = la_i + ((la_g >> 1) << 3);
    const int b_coladd = (la_g & 1) << 3;

    for (int c = 0; c < NCH; c++) {
        const int stage = c % GSTAGES;
        cp_wait_group<GSTAGES - 2>();
        __syncthreads();

        const int nc = c + GSTAGES - 1;
        if (nc < NCH) load_chunk(nc, nc % GSTAGES);
        cp_commit();

        const uint32_t base = sb + stage * STB;
        const uint32_t Bbase = base + SEGS * TILE_B;

#pragma unroll
        for (int k16 = 0; k16 < 64; k16 += 16) {
            uint32_t bf[4][4];
#pragma unroll
            for (int nb = 0; nb < 4; nb++) {
                const int row = wn * 64 + nb * 16 + b_rowadd;
                const int col = k16 + b_coladd;
                ldmatrix_x4(bf[nb], Bbase + (uint32_t)(row * ROWP + col) * 2);
            }
#pragma unroll
            for (int seg = 0; seg < SEGS; seg++) {
                const uint32_t Abase = base + seg * TILE_B;
                uint32_t af[2][4];
#pragma unroll
                for (int mi = 0; mi < 2; mi++) {
                    const int row = wm * 32 + mi * 16 + a_rowadd;
                    const int col = k16 + a_coladd;
                    ldmatrix_x4(af[mi], Abase + (uint32_t)(row * ROWP + col) * 2);
                }
#pragma unroll
                for (int nb = 0; nb < 4; nb++)
#pragma unroll
                    for (int mi = 0; mi < 2; mi++) {
                        mma_f16(acc[mi][nb * 2 + 0], af[mi], bf[nb][0], bf[nb][1]);
                        mma_f16(acc[mi][nb * 2 + 1], af[mi], bf[nb][2], bf[nb][3]);
                    }
            }
        }
    }

    const int tq = lane >> 2;
    const int tr = lane & 3;
#pragma unroll
    for (int mi = 0; mi < 2; mi++) {
        const int row = m0 + wm * 32 + mi * 16 + tq;
#pragma unroll
        for (int ni = 0; ni < 8; ni++) {
            const int col = n0 + wn * 64 + ni * 8 + tr * 2;
            const float b0 = bias[col], b1 = bias[col + 1];
            float c00 = acc[mi][ni][0] + b0, c01 = acc[mi][ni][1] + b1;
            float c10 = acc[mi][ni][2] + b0, c11 = acc[mi][ni][3] + b1;
            if (C) {
                float2 v0; v0.x = c00; v0.y = c01;
                float2 v1; v1.x = c10; v1.y = c11;
                *(float2*)&C[(size_t)row * Nfull + col] = v0;
                *(float2*)&C[(size_t)(row + 8) * Nfull + col] = v1;
            }
            if (Ch || Cl) {
                __half h00 = __float2half_rn(c00);
                __half h01 = __float2half_rn(c01);
                __half h10 = __float2half_rn(c10);
                __half h11 = __float2half_rn(c11);
                if (Ch) {
                    *(__half2*)&Ch[(size_t)row * Nfull + col]       = __halves2half2(h00, h01);
                    *(__half2*)&Ch[(size_t)(row + 8) * Nfull + col] = __halves2half2(h10, h11);
                }
                if (Cl) {
                    __half l00 = __float2half_rn(c00 - __half2float(h00));
                    __half l01 = __float2half_rn(c01 - __half2float(h01));
                    __half l10 = __float2half_rn(c10 - __half2float(h10));
                    __half l11 = __float2half_rn(c11 - __half2float(h11));
                    *(__half2*)&Cl[(size_t)row * Nfull + col]       = __halves2half2(l00, l01);
                    *(__half2*)&Cl[(size_t)(row + 8) * Nfull + col] = __halves2half2(l10, l11);
                }
            }
        }
    }
}

// ---------------------------------------------------------------------------
// Split-K selection GEMM via mma.sync (validated k-chunk 32 form)
// ---------------------------------------------------------------------------
#define ROWPAD  40
#define TILE_BYTES (128 * ROWPAD * 2)      // 10240

__global__ __launch_bounds__(256, 2)
void gemm_sel_mma(const __half* __restrict__ SCTh, const __half* __restrict__ SCTl,
                  const __half* __restrict__ CTh, float* __restrict__ S1)
{
    constexpr int STB = 3 * TILE_BYTES;

    extern __shared__ char smem[];
    const uint32_t sb = (uint32_t)__cvta_generic_to_shared(smem);
    const int tid = threadIdx.x;
    const int lane = tid & 31;
    const int warp = tid >> 5;
    const int wm = warp >> 1;
    const int wn = warp & 1;
    const int m0 = blockIdx.y * 128;
    const int n0 = blockIdx.x * 128;
    const int b  = blockIdx.z / SPLITK_SEL;
    const int sl = blockIdx.z % SPLITK_SEL;
    const int kbeg = sl * (MTOK_B / SPLITK_SEL);
    const int NCH = (MTOK_B / SPLITK_SEL) >> 5;

    const __half* Ah = SCTh + (size_t)b * KSEL * MTOK_B;
    const __half* Al = SCTl + (size_t)b * KSEL * MTOK_B;
    const __half* B  = CTh  + (size_t)b * E_DIM * MTOK_B;
    float* C = S1 + (size_t)b * KSEL * E_DIM;

    const int lr0 = tid >> 1;
    const int ls0 = (tid & 1) << 1;

    float acc[2][8][4];
#pragma unroll
    for (int mi = 0; mi < 2; mi++)
#pragma unroll
        for (int ni = 0; ni < 8; ni++)
#pragma unroll
            for (int q = 0; q < 4; q++) acc[mi][ni][q] = 0.f;

    auto load_chunk = [&](int c, int stage) {
        const int kb = kbeg + (c << 5);
        const uint32_t base = sb + stage * STB;
#pragma unroll
        for (int j = 0; j < 2; j++) {
            const int s4 = ls0 + j;
            const uint32_t soff = (uint32_t)(lr0 * ROWPAD + s4 * 8) * 2;
            cp_async16(base + soff,
                       Ah + (size_t)(m0 + lr0) * MTOK_B + kb + s4 * 8);
            cp_async16(base + TILE_BYTES + soff,
                       Al + (size_t)(m0 + lr0) * MTOK_B + kb + s4 * 8);
            cp_async16(base + 2 * TILE_BYTES + soff,
                       B + (size_t)(n0 + lr0) * MTOK_B + kb + s4 * 8);
        }
    };

#pragma unroll
    for (int s = 0; s < GSTAGES - 1; s++) {
        if (s < NCH) load_chunk(s, s);
        cp_commit();
    }

    const int la_i = lane & 7;
    const int la_g = lane >> 3;
    const int a_rowadd = la_i + ((la_g & 1) << 3);
    const int a_coladd = (la_g >> 1) << 3;
    const int b_rowadd = la_i + ((la_g >> 1) << 3);
    const int b_coladd = (la_g & 1) << 3;

    for (int c = 0; c < NCH; c++) {
        const int stage = c % GSTAGES;
        cp_wait_group<GSTAGES - 2>();
        __syncthreads();

        const int nc = c + GSTAGES - 1;
        if (nc < NCH) load_chunk(nc, nc % GSTAGES);
        cp_commit();

        const uint32_t base = sb + stage * STB;
        const uint32_t Bbase = base + 2 * TILE_BYTES;

#pragma unroll
        for (int k16 = 0; k16 < 32; k16 += 16) {
            uint32_t bf[4][4];
#pragma unroll
            for (int nb = 0; nb < 4; nb++) {
                const int row = wn * 64 + nb * 16 + b_rowadd;
                const int col = k16 + b_coladd;
                ldmatrix_x4(bf[nb], Bbase + (uint32_t)(row * ROWPAD + col) * 2);
            }
#pragma unroll
            for (int seg = 0; seg < 2; seg++) {
                const uint32_t Abase = base + seg * TILE_BYTES;
                uint32_t af[2][4];
#pragma unroll
                for (int mi = 0; mi < 2; mi++) {
                    const int row = wm * 32 + mi * 16 + a_rowadd;
                    const int col = k16 + a_coladd;
                    ldmatrix_x4(af[mi], Abase + (uint32_t)(row * ROWPAD + col) * 2);
                }
#pragma unroll
                for (int nb = 0; nb < 4; nb++)
#pragma unroll
                    for (int mi = 0; mi < 2; mi++) {
                        mma_f16(acc[mi][nb * 2 + 0], af[mi], bf[nb][0], bf[nb][1]);
                        mma_f16(acc[mi][nb * 2 + 1], af[mi], bf[nb][2], bf[nb][3]);
                    }
            }
        }
    }

    const int tq = lane >> 2;
    const int tr = lane & 3;
#pragma unroll
    for (int mi = 0; mi < 2; mi++) {
        const int row = m0 + wm * 32 + mi * 16 + tq;
#pragma unroll
        for (int ni = 0; ni < 8; ni++) {
            const int col = n0 + wn * 64 + ni * 8 + tr * 2;
            atomicAdd(&C[(size_t)row * E_DIM + col],           acc[mi][ni][0]);
            atomicAdd(&C[(size_t)row * E_DIM + col + 1],       acc[mi][ni][1]);
            atomicAdd(&C[(size_t)(row + 8) * E_DIM + col],     acc[mi][ni][2]);
            atomicAdd(&C[(size_t)(row + 8) * E_DIM + col + 1], acc[mi][ni][3]);
        }
    }
}

// ---------------------------------------------------------------------------
// mma.sync spatial attention (S=256, step 1), flash-style online softmax.
// ---------------------------------------------------------------------------
#define AKS_BYTES  (256 * 72 * 2)
#define AVT_BYTES  (64 * 264 * 2)
#define ATTN_SMEM  (AKS_BYTES + AVT_BYTES + 512 * 4)   // 74704

__global__ __launch_bounds__(256)
void attn_mma(const __half* __restrict__ Q, const __half* __restrict__ K,
              const __half* __restrict__ V,
              __half* __restrict__ OutH,
              const float* __restrict__ rb, int ldx)
{
    const int h = blockIdx.x;
    const int g = blockIdx.y;
    const int qh = blockIdx.z;
    const int base_m = g * N_DIM;
    const size_t baseE = (size_t)base_m * ldx + h * D_DIM;

    extern __shared__ char sm8[];
    __half* Ks = (__half*)sm8;
    __half* Vt = (__half*)(sm8 + AKS_BYTES);
    float*  rbh = (float*)(sm8 + AKS_BYTES + AVT_BYTES);
    const uint32_t sKs = (uint32_t)__cvta_generic_to_shared(Ks);
    const uint32_t sVt = (uint32_t)__cvta_generic_to_shared(Vt);

    const int tid = threadIdx.x;
    const int lane = tid & 31;
    const int warp = tid >> 5;

    for (int i = tid; i < 128 * 8; i += 256) {
        int r = i >> 3, cs = i & 7;
        *(float4*)&Ks[r * 72 + cs * 8] =
            *(const float4*)(Q + baseE + (size_t)(qh * 128 + r) * ldx + cs * 8);
    }
    __syncthreads();

    const int la_i = lane & 7;
    const int la_g = lane >> 3;
    const int a_rowadd = la_i + ((la_g & 1) << 3);
    const int a_coladd = (la_g >> 1) << 3;
    const int b_rowadd = la_i + ((la_g >> 1) << 3);
    const int b_coladd = (la_g & 1) << 3;

    uint32_t Qf[4][4];
    const int wq = warp * 16;
#pragma unroll
    for (int kk = 0; kk < 4; kk++)
        ldmatrix_x4(Qf[kk], sKs + (uint32_t)((wq + a_rowadd) * 72 + kk * 16 + a_coladd) * 2);
    __syncthreads();

    for (int i = tid; i < 256 * 8; i += 256) {
        int r = i >> 3, cs = i & 7;
        *(float4*)&Ks[r * 72 + cs * 8] =
            *(const float4*)(K + baseE + (size_t)r * ldx + cs * 8);
    }
    for (int i = tid; i < 256 * 32; i += 256) {
        int t = i >> 5, d2 = i & 31;
        __half2 v = *(const __half2*)(V + baseE + (size_t)t * ldx + 2 * d2);
        Vt[(2 * d2) * 264 + t]     = __low2half(v);
        Vt[(2 * d2 + 1) * 264 + t] = __high2half(v);
    }
    for (int i = tid; i < 511; i += 256)
        rbh[i] = rb[(size_t)(MAXLEN - 256 + i) * H_DIM + h];
    __syncthreads();

    const int tq = lane >> 2;
    const int tr = lane & 3;
    const int r0 = qh * 128 + wq + tq;
    const int r1 = r0 + 8;

    float o[8][4];
#pragma unroll
    for (int j = 0; j < 8; j++)
#pragma unroll
        for (int q = 0; q < 4; q++) o[j][q] = 0.f;
    float m0 = -1e30f, m1 = -1e30f, l0 = 0.f, l1 = 0.f;

#pragma unroll
    for (int ch = 0; ch < 4; ch++) {
        float s[8][4];
#pragma unroll
        for (int j = 0; j < 8; j++)
#pragma unroll
            for (int q = 0; q < 4; q++) s[j][q] = 0.f;

#pragma unroll
        for (int kk = 0; kk < 4; kk++) {
#pragma unroll
            for (int nb = 0; nb < 4; nb++) {
                uint32_t bf[4];
                ldmatrix_x4(bf, sKs + (uint32_t)((ch * 64 + nb * 16 + b_rowadd) * 72
                                                 + kk * 16 + b_coladd) * 2);
                mma_f16(s[nb * 2 + 0], Qf[kk], bf[0], bf[1]);
                mma_f16(s[nb * 2 + 1], Qf[kk], bf[2], bf[3]);
            }
        }

        float cm0 = -1e30f, cm1 = -1e30f;
#pragma unroll
        for (int j = 0; j < 8; j++) {
            const int c = ch * 64 + j * 8 + 2 * tr;
            s[j][0] = s[j][0] * 0.125f + rbh[c - r0 + 255];
            s[j][1] = s[j][1] * 0.125f + rbh[c + 1 - r0 + 255];
            s[j][2] = s[j][2] * 0.125f + rbh[c - r1 + 255];
            s[j][3] = s[j][3] * 0.125f + rbh[c + 1 - r1 + 255];
            cm0 = fmaxf(cm0, fmaxf(s[j][0], s[j][1]));
            cm1 = fmaxf(cm1, fmaxf(s[j][2], s[j][3]));
        }
        cm0 = fmaxf(cm0, __shfl_xor_sync(0xffffffffu, cm0, 1));
        cm0 = fmaxf(cm0, __shfl_xor_sync(0xffffffffu, cm0, 2));
        cm1 = fmaxf(cm1, __shfl_xor_sync(0xffffffffu, cm1, 1));
        cm1 = fmaxf(cm1, __shfl_xor_sync(0xffffffffu, cm1, 2));

        const float nm0 = fmaxf(m0, cm0), nm1 = fmaxf(m1, cm1);
        const float sc0 = __expf(m0 - nm0), sc1 = __expf(m1 - nm1);
        float rs0 = 0.f, rs1 = 0.f;
#pragma unroll
        for (int j = 0; j < 8; j++) {
            s[j][0] = __expf(s[j][0] - nm0);
            s[j][1] = __expf(s[j][1] - nm0);
            s[j][2] = __expf(s[j][2] - nm1);
            s[j][3] = __expf(s[j][3] - nm1);
            rs0 += s[j][0] + s[j][1];
            rs1 += s[j][2] + s[j][3];
        }
        rs0 += __shfl_xor_sync(0xffffffffu, rs0, 1);
        rs0 += __shfl_xor_sync(0xffffffffu, rs0, 2);
        rs1 += __shfl_xor_sync(0xffffffffu, rs1, 1);
        rs1 += __shfl_xor_sync(0xffffffffu, rs1, 2);
        l0 = l0 * sc0 + rs0;
        l1 = l1 * sc1 + rs1;
        m0 = nm0; m1 = nm1;
#pragma unroll
        for (int j = 0; j < 8; j++) {
            o[j][0] *= sc0; o[j][1] *= sc0;
            o[j][2] *= sc1; o[j][3] *= sc1;
        }

        uint32_t pa[4][4];
#pragma unroll
        for (int kk = 0; kk < 4; kk++) {
            pa[kk][0] = h2pack(s[2 * kk][0], s[2 * kk][1]);
            pa[kk][1] = h2pack(s[2 * kk][2], s[2 * kk][3]);
            pa[kk][2] = h2pack(s[2 * kk + 1][0], s[2 * kk + 1][1]);
            pa[kk][3] = h2pack(s[2 * kk + 1][2], s[2 * kk + 1][3]);
        }

#pragma unroll
        for (int kk = 0; kk < 4; kk++) {
#pragma unroll
            for (int nb = 0; nb < 4; nb++) {
                uint32_t bf[4];
                ldmatrix_x4(bf, sVt + (uint32_t)((nb * 16 + b_rowadd) * 264
                                                 + ch * 64 + kk * 16 + b_coladd) * 2);
                mma_f16(o[nb * 2 + 0], pa[kk], bf[0], bf[1]);
                mma_f16(o[nb * 2 + 1], pa[kk], bf[2], bf[3]);
            }
        }
    }

    const float inv0 = 1.f / l0, inv1 = 1.f / l1;
    const size_t oo0 = (size_t)(base_m + r0) * E_DIM + h * D_DIM;
    const size_t oo1 = (size_t)(base_m + r1) * E_DIM + h * D_DIM;
#pragma unroll
    for (int j = 0; j < 8; j++) {
        const int c = j * 8 + 2 * tr;
        *(__half2*)&OutH[oo0 + c] =
            __floats2half2_rn(o[j][0] * inv0, o[j][1] * inv0);
        *(__half2*)&OutH[oo1 + c] =
            __floats2half2_rn(o[j][2] * inv1, o[j][3] * inv1);
    }
}

// ---------------------------------------------------------------------------
// mma.sync temporal attention (S=32, step N_DIM): one warp per (h,b,n) group.
// ---------------------------------------------------------------------------
#define TBUF_HALVES 2560
#define ATTN_T_SMEM (8 * TBUF_HALVES * 2 + 64 * 4)   // 41216

__global__ __launch_bounds__(256)
void attn_mma_t(const __half* __restrict__ Q, const __half* __restrict__ K,
                const __half* __restrict__ V,
                __half* __restrict__ OutH,
                const float* __restrict__ rb, int ldx)
{
    const int h = blockIdx.x;
    const int tid = threadIdx.x;
    const int lane = tid & 31;
    const int warp = tid >> 5;
    const int g = blockIdx.y * 8 + warp;
    const int b = g >> 8, n = g & 255;
    const int base_m = b * MTOK_B + n;
    const size_t baseE = (size_t)base_m * ldx + h * D_DIM;
    const size_t stepE = (size_t)N_DIM * ldx;

    extern __shared__ char smT[];
    __half* buf = (__half*)smT + warp * TBUF_HALVES;
    float* rbh = (float*)(smT + 8 * TBUF_HALVES * 2);
    const uint32_t sb = (uint32_t)__cvta_generic_to_shared(buf);

    for (int i = tid; i < 63; i += 256)
        rbh[i] = rb[(size_t)(MAXLEN - 32 + i) * H_DIM + h];
    __syncthreads();

    const int la_i = lane & 7;
    const int la_g = lane >> 3;
    const int a_rowadd = la_i + ((la_g & 1) << 3);
    const int a_coladd = (la_g >> 1) << 3;
    const int b_rowadd = la_i + ((la_g >> 1) << 3);
    const int b_coladd = (la_g & 1) << 3;
    const int tq = lane >> 2;
    const int tr = lane & 3;

#pragma unroll
    for (int j = 0; j < 8; j++) {
        int idx = lane + j * 32;
        int r = idx >> 3, cs = idx & 7;
        *(float4*)&buf[r * 72 + cs * 8] =
            *(const float4*)(Q + baseE + (size_t)r * stepE + cs * 8);
    }
    __syncwarp();
    uint32_t Qf[2][4][4];
#pragma unroll
    for (int mi = 0; mi < 2; mi++)
#pragma unroll
        for (int kk = 0; kk < 4; kk++)
            ldmatrix_x4(Qf[mi][kk],
                        sb + (uint32_t)((mi * 16 + a_rowadd) * 72 + kk * 16 + a_coladd) * 2);
    __syncwarp();

#pragma unroll
    for (int j = 0; j < 8; j++) {
        int idx = lane + j * 32;
        int r = idx >> 3, cs = idx & 7;
        *(float4*)&buf[r * 72 + cs * 8] =
            *(const float4*)(K + baseE + (size_t)r * stepE + cs * 8);
    }
    __syncwarp();

    float s[2][4][4];
#pragma unroll
    for (int mi = 0; mi < 2; mi++)
#pragma unroll
        for (int ni = 0; ni < 4; ni++)
#pragma unroll
            for (int q = 0; q < 4; q++) s[mi][ni][q] = 0.f;

#pragma unroll
    for (int kk = 0; kk < 4; kk++)
#pragma unroll
        for (int nb = 0; nb < 2; nb++) {
            uint32_t bf[4];
            ldmatrix_x4(bf, sb + (uint32_t)((nb * 16 + b_rowadd) * 72 + kk * 16 + b_coladd) * 2);
#pragma unroll
            for (int mi = 0; mi < 2; mi++) {
                mma_f16(s[mi][nb * 2 + 0], Qf[mi][kk], bf[0], bf[1]);
                mma_f16(s[mi][nb * 2 + 1], Qf[mi][kk], bf[2], bf[3]);
            }
        }
    __syncwarp();

#pragma unroll
    for (int j = 0; j < 32; j++) {
        __half2 v = *(const __half2*)(V + baseE + (size_t)j * stepE + 2 * lane);
        buf[(2 * lane) * 40 + j]     = __low2half(v);
        buf[(2 * lane + 1) * 40 + j] = __high2half(v);
    }
    __syncwarp();

#pragma unroll
    for (int mi = 0; mi < 2; mi++) {
        const int ra = mi * 16 + tq, rb2 = ra + 8;
        float mxa = -1e30f, mxb = -1e30f;
#pragma unroll
        for (int ni = 0; ni < 4; ni++) {
            const int c = ni * 8 + 2 * tr;
            s[mi][ni][0] = s[mi][ni][0] * 0.125f + rbh[c - ra + 31];
            s[mi][ni][1] = s[mi][ni][1] * 0.125f + rbh[c + 1 - ra + 31];
            s[mi][ni][2] = s[mi][ni][2] * 0.125f + rbh[c - rb2 + 31];
            s[mi][ni][3] = s[mi][ni][3] * 0.125f + rbh[c + 1 - rb2 + 31];
            mxa = fmaxf(mxa, fmaxf(s[mi][ni][0], s[mi][ni][1]));
            mxb = fmaxf(mxb, fmaxf(s[mi][ni][2], s[mi][ni][3]));
        }
        mxa = fmaxf(mxa, __shfl_xor_sync(0xffffffffu, mxa, 1));
        mxa = fmaxf(mxa, __shfl_xor_sync(0xffffffffu, mxa, 2));
        mxb = fmaxf(mxb, __shfl_xor_sync(0xffffffffu, mxb, 1));
        mxb = fmaxf(mxb, __shfl_xor_sync(0xffffffffu, mxb, 2));
        float sa = 0.f, sbm = 0.f;
#pragma unroll
        for (int ni = 0; ni < 4; ni++) {
            s[mi][ni][0] = __expf(s[mi][ni][0] - mxa);
            s[mi][ni][1] = __expf(s[mi][ni][1] - mxa);
            s[mi][ni][2] = __expf(s[mi][ni][2] - mxb);
            s[mi][ni][3] = __expf(s[mi][ni][3] - mxb);
            sa += s[mi][ni][0] + s[mi][ni][1];
            sbm += s[mi][ni][2] + s[mi][ni][3];
        }
        sa += __shfl_xor_sync(0xffffffffu, sa, 1);
        sa += __shfl_xor_sync(0xffffffffu, sa, 2);
        sbm += __shfl_xor_sync(0xffffffffu, sbm, 1);
        sbm += __shfl_xor_sync(0xffffffffu, sbm, 2);
        const float ia = 1.f / sa, ib = 1.f / sbm;
#pragma unroll
        for (int ni = 0; ni < 4; ni++) {
            s[mi][ni][0] *= ia; s[mi][ni][1] *= ia;
            s[mi][ni][2] *= ib; s[mi][ni][3] *= ib;
        }
    }

    uint32_t pa[2][2][4];
#pragma unroll
    for (int mi = 0; mi < 2; mi++)
#pragma unroll
        for (int kk = 0; kk < 2; kk++) {
            pa[mi][kk][0] = h2pack(s[mi][2 * kk][0], s[mi][2 * kk][1]);
            pa[mi][kk][1] = h2pack(s[mi][2 * kk][2], s[mi][2 * kk][3]);
            pa[mi][kk][2] = h2pack(s[mi][2 * kk + 1][0], s[mi][2 * kk + 1][1]);
            pa[mi][kk][3] = h2pack(s[mi][2 * kk + 1][2], s[mi][2 * kk + 1][3]);
        }

    float o[2][8][4];
#pragma unroll
    for (int mi = 0; mi < 2; mi++)
#pragma unroll
        for (int ni = 0; ni < 8; ni++)
#pragma unroll
            for (int q = 0; q < 4; q++) o[mi][ni][q] = 0.f;

#pragma unroll
    for (int kk = 0; kk < 2; kk++)
#pragma unroll
        for (int nb = 0; nb < 4; nb++) {
            uint32_t bf[4];
            ldmatrix_x4(bf, sb + (uint32_t)((nb * 16 + b_rowadd) * 40 + kk * 16 + b_coladd) * 2);
#pragma unroll
            for (int mi = 0; mi < 2; mi++) {
                mma_f16(o[mi][nb * 2 + 0], pa[mi][kk], bf[0], bf[1]);
                mma_f16(o[mi][nb * 2 + 1], pa[mi][kk], bf[2], bf[3]);
            }
        }

#pragma unroll
    for (int mi = 0; mi < 2; mi++) {
        const int ra = mi * 16 + tq;
        const size_t oo0 = (size_t)(base_m + ra * N_DIM) * E_DIM + h * D_DIM;
        const size_t oo1 = (size_t)(base_m + (ra + 8) * N_DIM) * E_DIM + h * D_DIM;
#pragma unroll
        for (int ni = 0; ni < 8; ni++) {
            const int c = ni * 8 + 2 * tr;
            *(__half2*)&OutH[oo0 + c] = __floats2half2_rn(o[mi][ni][0], o[mi][ni][1]);
            *(__half2*)&OutH[oo1 + c] = __floats2half2_rn(o[mi][ni][2], o[mi][ni][3]);
        }
    }
}

// ---------------------------------------------------------------------------
// misc elementwise / prep kernels
// ---------------------------------------------------------------------------
__global__ void cvt_hilo(const float* __restrict__ x, __half* __restrict__ hi,
                         __half* __restrict__ lo, int n4)
{
    int i = blockIdx.x * blockDim.x + threadIdx.x;
    if (i >= n4) return;
    float4 v = ((const float4*)x)[i];
    __half h0 = __float2half_rn(v.x);
    __half h1 = __float2half_rn(v.y);
    __half h2 = __float2half_rn(v.z);
    __half h3 = __float2half_rn(v.w);
    __half l0 = __float2half_rn(v.x - __half2float(h0));
    __half l1 = __float2half_rn(v.y - __half2float(h1));
    __half l2 = __float2half_rn(v.z - __half2float(h2));
    __half l3 = __float2half_rn(v.w - __half2float(h3));
    __half2* hp = (__half2*)hi;
    __half2* lp = (__half2*)lo;
    hp[2 * i + 0] = __half2(h0, h1);
    hp[2 * i + 1] = __half2(h2, h3);
    lp[2 * i + 0] = __half2(l0, l1);
    lp[2 * i + 1] = __half2(l2, l3);
}

__global__ void cvt_f16(const float* __restrict__ x, __half* __restrict__ y, int n4)
{
    int i = blockIdx.x * blockDim.x + threadIdx.x;
    if (i >= n4) return;
    float4 v = ((const float4*)x)[i];
    __half2* yp = (__half2*)y;
    yp[2 * i + 0] = __floats2half2_rn(v.x, v.y);
    yp[2 * i + 1] = __floats2half2_rn(v.z, v.w);
}

// Weight transpose + fp16 hi/lo convert; z-index offset by zbase.
__global__ void wt_cvt3(const float* __restrict__ W, __half* __restrict__ WTh,
                        __half* __restrict__ WTl, int Kd, int Nd, int type, int slots,
                        int zbase)
{
    __shared__ float t[32][33];
    const int z = blockIdx.z + zbase;
    const size_t srcoff = (size_t)z * Kd * Nd;
    const size_t dstoff = ((size_t)z * slots + type) * Kd * Nd;
    const float* Wm = W + srcoff;
    __half* Hh = WTh + dstoff;
    __half* Hl = WTl + dstoff;

    int nx = blockIdx.x * 32 + threadIdx.x;
    int k0 = blockIdx.y * 32;
#pragma unroll
    for (int j = 0; j < 4; j++) {
        int kk = k0 + threadIdx.y + j * 8;
        t[threadIdx.y + j * 8][threadIdx.x] = Wm[(size_t)kk * Nd + nx];
    }
    __syncthreads();
    int kx = k0 + threadIdx.x;
#pragma unroll
    for (int j = 0; j < 4; j++) {
        int nn = blockIdx.x * 32 + threadIdx.y + j * 8;
        float v = t[threadIdx.x][threadIdx.y + j * 8];
        __half h = __float2half_rn(v);
        Hh[(size_t)nn * Kd + kx] = h;
        Hl[(size_t)nn * Kd + kx] = __float2half_rn(v - __half2float(h));
    }
}

__global__ void wt_cvt(const float* __restrict__ W, __half* __restrict__ WT,
                       int Kd, int Nd)
{
    __shared__ float t[32][33];
    const size_t moff = (size_t)blockIdx.z * Kd * Nd;
    const float* Wm = W + moff;
    __half* Hh = WT + moff;

    int nx = blockIdx.x * 32 + threadIdx.x;
    int k0 = blockIdx.y * 32;
#pragma unroll
    for (int j = 0; j < 4; j++) {
        int kk = k0 + threadIdx.y + j * 8;
        t[threadIdx.y + j * 8][threadIdx.x] = Wm[(size_t)kk * Nd + nx];
    }
    __syncthreads();
    int kx = k0 + threadIdx.x;
#pragma unroll
    for (int j = 0; j < 4; j++) {
        int nn = blockIdx.x * 32 + threadIdx.y + j * 8;
        Hh[(size_t)nn * Kd + kx] = __float2half_rn(t[threadIdx.x][threadIdx.y + j * 8]);
    }
}

// transpose + hi/lo split: src fp32 [z][R][C] -> dst fp16 [z][C][R]
__global__ void transp_hilo(const float* __restrict__ src, __half* __restrict__ dh,
                            __half* __restrict__ dl, int R, int C)
{
    __shared__ float t[32][33];
    const size_t zo = (size_t)blockIdx.z * R * C;
    const float* S = src + zo;
    __half* Dh = dh + zo;
    __half* Dl = dl ? dl + zo : nullptr;

    int cx = blockIdx.x * 32 + threadIdx.x;
    int r0 = blockIdx.y * 32;
#pragma unroll
    for (int j = 0; j < 4; j++) {
        int rr = r0 + threadIdx.y + j * 8;
        t[threadIdx.y + j * 8][threadIdx.x] = S[(size_t)rr * C + cx];
    }
    __syncthreads();
    int rx = r0 + threadIdx.x;
#pragma unroll
    for (int j = 0; j < 4; j++) {
        int cc = blockIdx.x * 32 + threadIdx.y + j * 8;
        float v = t[threadIdx.x][threadIdx.y + j * 8];
        __half h = __float2half_rn(v);
        Dh[(size_t)cc * R + rx] = h;
        if (Dl) Dl[(size_t)cc * R + rx] = __float2half_rn(v - __half2float(h));
    }
}

// fp16 transpose: src fp16 [z][R][C] -> dst fp16 [z][C][R]
__global__ void transp_h16(const __half* __restrict__ src, __half* __restrict__ dst,
                           int R, int C)
{
    __shared__ __half t[32][33];
    const size_t zo = (size_t)blockIdx.z * R * C;
    const __half* S = src + zo;
    __half* D = dst + zo;

    int cx = blockIdx.x * 32 + threadIdx.x;
    int r0 = blockIdx.y * 32;
#pragma unroll
    for (int j = 0; j < 4; j++) {
        int rr = r0 + threadIdx.y + j * 8;
        t[threadIdx.y + j * 8][threadIdx.x] = S[(size_t)rr * C + cx];
    }
    __syncthreads();
    int rx = r0 + threadIdx.x;
#pragma unroll
    for (int j = 0; j < 4; j++) {
        int cc = blockIdx.x * 32 + threadIdx.y + j * 8;
        D[(size_t)cc * R + rx] = t[threadIdx.x][threadIdx.y + j * 8];
    }
}

__global__ void bias_concat(const float* __restrict__ bq, const float* __restrict__ bk,
                            const float* __restrict__ bv, float* __restrict__ out)
{
    int i = blockIdx.x * blockDim.x + threadIdx.x;
    if (i >= 4 * QKV_N) return;
    int a = i / QKV_N;
    int r = i % QKV_N;
    const float* src = (r < E_DIM) ? bq : (r < 2 * E_DIM) ? bk : bv;
    out[i] = src[a * E_DIM + (r & (E_DIM - 1))];
}

__global__ void bias_comb(const float* __restrict__ wq, const float* __restrict__ wk,
                          const float* __restrict__ wv, const float* __restrict__ bd,
                          const float* __restrict__ bqkv, float* __restrict__ out)
{
    int i = blockIdx.x * blockDim.x + threadIdx.x;
    int z = blockIdx.y;
    const float* W = (i < E_DIM) ? wq : (i < 2 * E_DIM) ? wk : wv;
    int col = i & (E_DIM - 1);
    const float* Wm = W + (size_t)(z + 1) * E_DIM * E_DIM;
    const float* bdz = bd + (size_t)z * E_DIM;
    float s = 0.f;
    for (int k = 0; k < E_DIM; k++)
        s += bdz[k] * Wm[(size_t)k * E_DIM + col];
    out[(size_t)z * QKV_N + i] = s + bqkv[(size_t)(z + 1) * QKV_N + i];
}

__global__ void bias_sel(const float* __restrict__ selw, const float* __restrict__ selb,
                         const float* __restrict__ bd3, float* __restrict__ out)
{
    int k = blockIdx.x * blockDim.x + threadIdx.x;
    if (k >= KSEL) return;
    float s = 0.f;
    for (int e = 0; e < E_DIM; e++)
        s += bd3[e] * selw[(size_t)e * KSEL + k];
    out[k] = s + selb[k];
}

// ---------------------------------------------------------------------------
// Selection softmax / pooling
// ---------------------------------------------------------------------------
__global__ __launch_bounds__(256)
void sel_softmax(float* __restrict__ sc)
{
    const int b = blockIdx.x;
    const int k0 = blockIdx.y * 32;
    const int lane = threadIdx.x & 31;
    const int row = threadIdx.x >> 5;

    float* base = sc + (size_t)b * MTOK_B * KSEL + k0 + lane;

    __shared__ float redA[8][32];
    __shared__ float redB[8][32];

    float mx = -1e30f;
    for (int m = row; m < MTOK_B; m += 8)
        mx = fmaxf(mx, base[(size_t)m * KSEL]);
    redA[row][lane] = mx;
    __syncthreads();
    if (row == 0) {
        float v = redA[0][lane];
#pragma unroll
        for (int r = 1; r < 8; r++) v = fmaxf(v, redA[r][lane]);
        redA[0][lane] = v;
    }
    __syncthreads();
    mx = redA[0][lane];

    float sum = 0.f;
    for (int m = row; m < MTOK_B; m += 8)
        sum += __expf(base[(size_t)m * KSEL] - mx);
    redB[row][lane] = sum;
    __syncthreads();
    if (row == 0) {
        float v = 0.f;
#pragma unroll
        for (int r = 0; r < 8; r++) v += redB[r][lane];
        redB[0][lane] = v;
    }
    __syncthreads();
    float inv = 1.f / redB[0][lane];

    for (int m = row; m < MTOK_B; m += 8) {
        float* p = &base[(size_t)m * KSEL];
        *p = __expf(*p - mx) * inv;
    }
}

__global__ void pool_kernel(const float* __restrict__ sel, float* __restrict__ out)
{
    int idx = blockIdx.x * blockDim.x + threadIdx.x;
    int total = B_DIM * OUT_ROWS * E_DIM;
    if (idx >= total) return;
    int e = idx % E_DIM;
    int r = (idx / E_DIM) % OUT_ROWS;
    int b = idx / (OUT_ROWS * E_DIM);
    const float* sb = sel + (size_t)b * KSEL * E_DIM;
    float v;
    if (r < 256) {
        v = sb[(size_t)r * E_DIM + e];
    } else if (r < 384) {
        int i = (r - 256) * 2;
        v = 0.5f * (sb[(size_t)i * E_DIM + e] + sb[(size_t)(i + 1) * E_DIM + e]);
    } else {
        int i = (r - 384) * 4;
        v = 0.25f * (sb[(size_t)i * E_DIM + e] + sb[(size_t)(i + 1) * E_DIM + e] +
                     sb[(size_t)(i + 2) * E_DIM + e] + sb[(size_t)(i + 3) * E_DIM + e]);
    }
    out[idx] = v;
}

// ---------------------------------------------------------------------------
// Orchestration
// ---------------------------------------------------------------------------
extern "C" void kernel_launch(void* const* d_in, const int* in_sizes, int n_in,
                              void* d_out, int out_size)
{
    (void)in_sizes; (void)n_in; (void)out_size;

    const float* x    = (const float*)d_in[0];
    const float* wq   = (const float*)d_in[1];
    const float* bq   = (const float*)d_in[2];
    const float* wk   = (const float*)d_in[3];
    const float* bk   = (const float*)d_in[4];
    const float* wv   = (const float*)d_in[5];
    const float* bv   = (const float*)d_in[6];
    const float* wd   = (const float*)d_in[7];
    const float* bd   = (const float*)d_in[8];
    const float* rb   = (const float*)d_in[9];
    const float* selw = (const float*)d_in[10];
    const float* selb = (const float*)d_in[11];
    float* out = (float*)d_out;

    float *SCb, *S1b, *SELb, *Bqkv, *Bcomb, *Bias2, *Bzero;
    cudaGetSymbolAddress((void**)&SCb, g_SC);
    cudaGetSymbolAddress((void**)&S1b, g_S1);
    cudaGetSymbolAddress((void**)&SELb, g_SEL);
    cudaGetSymbolAddress((void**)&Bqkv, g_Bqkv);
    cudaGetSymbolAddress((void**)&Bcomb, g_Bcomb);
    cudaGetSymbolAddress((void**)&Bias2, g_Bias2);
    cudaGetSymbolAddress((void**)&Bzero, g_Bzero);

    __half *QKVh, *Ahp, *Ah2p, *Al2p, *WqkvTh, *WqkvTl, *Wd16, *WdT3, *WcT;
    __half *SWTh, *SWTl, *Bsel, *SCTh, *SCTl, *CTh;
    cudaGetSymbolAddress((void**)&QKVh, g_QKVh);
    cudaGetSymbolAddress((void**)&Ahp, g_Ah);
    cudaGetSymbolAddress((void**)&Ah2p, g_Ah2);
    cudaGetSymbolAddress((void**)&Al2p, g_Al2);
    cudaGetSymbolAddress((void**)&WqkvTh, g_WqkvTh);
    cudaGetSymbolAddress((void**)&WqkvTl, g_WqkvTl);
    cudaGetSymbolAddress((void**)&Wd16, g_Wd16);
    cudaGetSymbolAddress((void**)&WdT3, g_WdT3);
    cudaGetSymbolAddress((void**)&WcT, g_WcT);
    cudaGetSymbolAddress((void**)&SWTh, g_SWTh);
    cudaGetSymbolAddress((void**)&SWTl, g_SWTl);
    cudaGetSymbolAddress((void**)&Bsel, g_Bsel);
    cudaGetSymbolAddress((void**)&SCTh, g_SCTh);
    cudaGetSymbolAddress((void**)&SCTl, g_SCTl);
    cudaGetSymbolAddress((void**)&CTh, g_CTh);

    static cudaStream_t s2 = nullptr;
    static cudaEvent_t evF = nullptr, evJ = nullptr, evA = nullptr, evT = nullptr;
    if (!s2) {
        cudaStreamCreateWithFlags(&s2, cudaStreamNonBlocking);
        cudaEventCreateWithFlags(&evF, cudaEventDisableTiming);
        cudaEventCreateWithFlags(&evJ, cudaEventDisableTiming);
        cudaEventCreateWithFlags(&evA, cudaEventDisableTiming);
        cudaEventCreateWithFlags(&evT, cudaEventDisableTiming);
    }

    const int SMEM1 = GSTAGES * 2 * TILE_B;    // 110592
    const int SMEM2 = GSTAGES * 3 * TILE_B;    // 165888
    const int SMEM_SEL = GSTAGES * 3 * TILE_BYTES;   // 92160
    cudaFuncSetAttribute((const void*)attn_mma,
                         cudaFuncAttributeMaxDynamicSharedMemorySize, ATTN_SMEM);
    cudaFuncSetAttribute((const void*)attn_mma_t,
                         cudaFuncAttributeMaxDynamicSharedMemorySize, ATTN_T_SMEM);
    cudaFuncSetAttribute((const void*)gemm_f16<1>,
                         cudaFuncAttributeMaxDynamicSharedMemorySize, SMEM1);
    cudaFuncSetAttribute((const void*)gemm_f16<2>,
                         cudaFuncAttributeMaxDynamicSharedMemorySize, SMEM2);
    cudaFuncSetAttribute((const void*)gemm_sel_mma,
                         cudaFuncAttributeMaxDynamicSharedMemorySize, SMEM_SEL);

    const dim3 blk(256);
    const dim3 tblk(32, 8);
    const int n4 = MTOK * E_DIM / 4;
    const dim3 gcvt((n4 + 255) / 256);
    const dim3 gQKV(QKV_N / 128, MTOK / 128);
    const size_t MM = (size_t)E_DIM * E_DIM;
    const size_t MM3 = 3 * MM;
    const size_t WCS = (size_t)QKV_N * E_DIM;

    // ---- main stream: layer-0 weights only (z=0) ----
    wt_cvt3<<<dim3(E_DIM / 32, E_DIM / 32, 1), tblk>>>(wq, WqkvTh, WqkvTl, E_DIM, E_DIM, 0, 3, 0);
    wt_cvt3<<<dim3(E_DIM / 32, E_DIM / 32, 1), tblk>>>(wk, WqkvTh, WqkvTl, E_DIM, E_DIM, 1, 3, 0);
    wt_cvt3<<<dim3(E_DIM / 32, E_DIM / 32, 1), tblk>>>(wv, WqkvTh, WqkvTl, E_DIM, E_DIM, 2, 3, 0);
    bias_concat<<<(4 * QKV_N + 255) / 256, blk>>>(bq, bk, bv, Bqkv);

    // ---- fork: layers 1-3 weight conversion + fold prep on s2 ----
    cudaEventRecord(evF, 0);
    cudaStreamWaitEvent(s2, evF, 0);

    wt_cvt3<<<dim3(E_DIM / 32, E_DIM / 32, 3), tblk, 0, s2>>>(wq, WqkvTh, WqkvTl, E_DIM, E_DIM, 0, 3, 1);
    wt_cvt3<<<dim3(E_DIM / 32, E_DIM / 32, 3), tblk, 0, s2>>>(wk, WqkvTh, WqkvTl, E_DIM, E_DIM, 1, 3, 1);
    wt_cvt3<<<dim3(E_DIM / 32, E_DIM / 32, 3), tblk, 0, s2>>>(wv, WqkvTh, WqkvTl, E_DIM, E_DIM, 2, 3, 1);
    cvt_f16<<<(int)((4 * MM / 4 + 255) / 256), blk, 0, s2>>>(wd, Wd16, (int)(4 * MM / 4));
    gemm_f16<2><<<dim3(E_DIM / 128, QKV_N / 128, 3), blk, SMEM2, s2>>>(
        WqkvTh + MM3, WqkvTl + MM3, Wd16, Bzero, nullptr,
        WcT, nullptr, E_DIM, E_DIM, MM3, MM, WCS);
    wt_cvt<<<dim3(E_DIM / 32, E_DIM / 32, 1), tblk, 0, s2>>>(wd + 3 * MM, WdT3, E_DIM, E_DIM);
    wt_cvt3<<<dim3(KSEL / 32, E_DIM / 32, 1), tblk, 0, s2>>>(selw, SWTh, SWTl, E_DIM, KSEL, 0, 1, 0);
    gemm_f16<2><<<dim3(E_DIM / 128, KSEL / 128), blk, SMEM2, s2>>>(
        SWTh, SWTl, Wd16 + 3 * MM, Bzero, nullptr,
        Bsel, nullptr, E_DIM, E_DIM, 0, 0, 0);
    bias_comb<<<dim3(QKV_N / 256, 3), blk, 0, s2>>>(wq, wk, wv, bd, Bqkv, Bcomb);
    bias_sel<<<1, 256, 0, s2>>>(selw, selb, bd + 3 * E_DIM, Bias2);
    cudaMemsetAsync(S1b, 0, (size_t)B_DIM * KSEL * E_DIM * sizeof(float), s2);
    cudaEventRecord(evJ, s2);

    // ---- main stream: layer 0 (x hi only; lo is dead for SEGS=1 GEMM) ----
    cvt_f16<<<gcvt, blk>>>(x, Ah2p, n4);
    gemm_f16<1><<<gQKV, blk, SMEM1>>>(Ah2p, nullptr, WqkvTh, Bqkv, nullptr,
                                      QKVh, nullptr, QKV_N, E_DIM, 0, 0, 0);
    attn_mma<<<dim3(H_DIM, B_DIM * T_DIM, 2), blk, ATTN_SMEM>>>(
        QKVh, QKVh + E_DIM, QKVh + 2 * E_DIM, Ahp, rb, QKV_N);

    // ---- join: folded weights ready before layer 1 ----
    cudaStreamWaitEvent(0, evJ, 0);

    for (int a = 1; a < 4; a++) {
        gemm_f16<1><<<gQKV, blk, SMEM1>>>(Ahp, nullptr, WcT + (a - 1) * WCS,
                                          Bcomb + (size_t)(a - 1) * QKV_N, nullptr,
                                          QKVh, nullptr, QKV_N, E_DIM, 0, 0, 0);

        const float* rba = rb + (size_t)a * RB_ONE;
        if ((a & 1) == 0) {
            attn_mma<<<dim3(H_DIM, B_DIM * T_DIM, 2), blk, ATTN_SMEM>>>(
                QKVh, QKVh + E_DIM, QKVh + 2 * E_DIM, Ahp, rba, QKV_N);
        } else {
            attn_mma_t<<<dim3(H_DIM, (B_DIM * N_DIM) / 8), blk, ATTN_T_SMEM>>>(
                QKVh, QKVh + E_DIM, QKVh + 2 * E_DIM, Ahp, rba, QKV_N);
        }
    }

    // ---- tail fork: ctx^T on s2 concurrent with score path on main ----
    cudaEventRecord(evA, 0);
    cudaStreamWaitEvent(s2, evA, 0);
    transp_h16<<<dim3(E_DIM / 32, MTOK_B / 32, B_DIM), tblk, 0, s2>>>(Ahp, CTh, MTOK_B, E_DIM);
    cudaEventRecord(evT, s2);

    // selection scores on ctx: SC = ctx_hi @ Bsel^T + Bias2
    gemm_f16<1><<<dim3(KSEL / 128, MTOK / 128), blk, SMEM1>>>(
        Ahp, nullptr, Bsel, Bias2, SCb, nullptr, nullptr, KSEL, E_DIM, 0, 0, 0);

    sel_softmax<<<dim3(B_DIM, KSEL / 32), blk>>>(SCb);

    transp_hilo<<<dim3(KSEL / 32, MTOK_B / 32, B_DIM), tblk>>>(SCb, SCTh, SCTl, MTOK_B, KSEL);

    // join ctx^T, then S1 = wts^T @ ctx  (mma split-K + fp32 atomics)
    cudaStreamWaitEvent(0, evT, 0);
    gemm_sel_mma<<<dim3(E_DIM / 128, KSEL / 128, B_DIM * SPLITK_SEL), blk, SMEM_SEL>>>(
        SCTh, SCTl, CTh, S1b);

    // SEL = S1 @ Wd3 + bd3  (tiny 2-seg GEMM)
    cvt_hilo<<<dim3((B_DIM * KSEL * E_DIM / 4 + 255) / 256), blk>>>(
        S1b, Ah2p, Al2p, B_DIM * KSEL * E_DIM / 4);
    gemm_f16<2><<<dim3(E_DIM / 128, (B_DIM * KSEL) / 128), blk, SMEM2>>>(
        Ah2p, Al2p, WdT3, bd + 3 * E_DIM, SELb, nullptr, nullptr, E_DIM, E_DIM, 0, 0, 0);

    int total = B_DIM * OUT_ROWS * E_DIM;
    pool_kernel<<<(total + 255) / 256, 256>>>(SELb, out);
}

// round 17
// speedup vs baseline: 1.0125x; 1.0125x over previous
#include <cuda_runtime.h>
#include <cuda_fp16.h>
#include <cstdint>
#include <cstddef>

// ---------------------------------------------------------------------------
// Problem constants
// ---------------------------------------------------------------------------
#define E_DIM   1024
#define QKV_N   3072
#define H_DIM   16
#define D_DIM   64
#define B_DIM   2
#define T_DIM   32
#define N_DIM   256
#define MTOK    (B_DIM * T_DIM * N_DIM)   // 16384 tokens total
#define MTOK_B  (T_DIM * N_DIM)           // 8192 tokens per batch
#define KSEL    256
#define MAXLEN  512
#define RB_ONE  ((2 * MAXLEN - 1) * H_DIM)
#define OUT_ROWS 448                      // 256 + 128 + 64
#define SPLITK_SEL 8

// ---------------------------------------------------------------------------
// Scratch (device globals — no allocations allowed)
// ---------------------------------------------------------------------------
__device__ __half g_QKVh[MTOK * QKV_N];   // merged Q|K|V per token, fp16
__device__ float g_SC[MTOK * KSEL];
__device__ float g_S1[B_DIM * KSEL * E_DIM];   // wts^T @ ctx
__device__ float g_SEL[B_DIM * KSEL * E_DIM];  // final selected tokens

// fp16 activations
__device__ __half g_Ah[MTOK * E_DIM];     // attention ctx (fp16)
__device__ __half g_Ah2[MTOK * E_DIM];
__device__ __half g_Al2[MTOK * E_DIM];
// transposed fp16 weights
__device__ __half g_WqkvTh[4 * 3 * E_DIM * E_DIM];  // [a][q|k|v][N=E][K=E] hi
__device__ __half g_WqkvTl[4 * 3 * E_DIM * E_DIM];  // lo
__device__ __half g_Wd16[4 * E_DIM * E_DIM];        // wd plain (row-major) fp16
__device__ __half g_WdT3[E_DIM * E_DIM];            // wd[3] transposed fp16
__device__ __half g_WcT[3 * QKV_N * E_DIM];         // combined W'^T fp16
__device__ __half g_SWTh[KSEL * E_DIM];             // selw^T hi
__device__ __half g_SWTl[KSEL * E_DIM];             // selw^T lo
__device__ __half g_Bsel[KSEL * E_DIM];             // (Wd3 @ selw)^T fp16
// selection mma operands
__device__ __half g_SCTh[B_DIM * KSEL * MTOK_B];    // wts^T hi
__device__ __half g_SCTl[B_DIM * KSEL * MTOK_B];    // wts^T lo
__device__ __half g_CTh[B_DIM * E_DIM * MTOK_B];    // ctx^T hi
__device__ float  g_Bqkv[4 * QKV_N];
__device__ float  g_Bcomb[3 * QKV_N];
__device__ float  g_Bias2[KSEL];
__device__ float  g_Bzero[E_DIM];

// ---------------------------------------------------------------------------
// PTX helpers
// ---------------------------------------------------------------------------
__device__ __forceinline__ void cp_async16(uint32_t dst, const void* src) {
    asm volatile("cp.async.cg.shared.global [%0], [%1], 16;" :: "r"(dst), "l"(src));
}
__device__ __forceinline__ void cp_commit() {
    asm volatile("cp.async.commit_group;" ::: "memory");
}
template <int N>
__device__ __forceinline__ void cp_wait_group() {
    asm volatile("cp.async.wait_group %0;" :: "n"(N) : "memory");
}
__device__ __forceinline__ void ldmatrix_x4(uint32_t* r, uint32_t addr) {
    asm volatile("ldmatrix.sync.aligned.m8n8.x4.shared.b16 {%0,%1,%2,%3}, [%4];"
                 : "=r"(r[0]), "=r"(r[1]), "=r"(r[2]), "=r"(r[3]) : "r"(addr));
}
__device__ __forceinline__ void mma_f16(float* d, const uint32_t* a,
                                        uint32_t b0, uint32_t b1) {
    asm volatile(
        "mma.sync.aligned.m16n8k16.row.col.f32.f16.f16.f32 "
        "{%0,%1,%2,%3}, {%4,%5,%6,%7}, {%8,%9}, {%0,%1,%2,%3};"
        : "+f"(d[0]), "+f"(d[1]), "+f"(d[2]), "+f"(d[3])
        : "r"(a[0]), "r"(a[1]), "r"(a[2]), "r"(a[3]), "r"(b0), "r"(b1));
}
__device__ __forceinline__ uint32_t h2pack(float a, float b) {
    __half2 h = __floats2half2_rn(a, b);
    return *(uint32_t*)&h;
}

// ---------------------------------------------------------------------------
// fp16 GEMM via mma.sync, k-chunk 64 (tile 128x64, row stride 72).
// ---------------------------------------------------------------------------
#define GSTAGES 3
#define ROWP  72
#define TILE_B (128 * ROWP * 2)            // 18432 per tile

template <int SEGS>
__global__ __launch_bounds__(256, 2)
void gemm_f16(const __half* __restrict__ Ah, const __half* __restrict__ Al,
              const __half* __restrict__ B,
              const float* __restrict__ bias, float* __restrict__ C,
              __half* __restrict__ Ch, __half* __restrict__ Cl,
              int Nfull, int Kfull,
              size_t zA, size_t zB, size_t zC)
{
    constexpr int STB = (SEGS + 1) * TILE_B;

    extern __shared__ char smem[];
    const uint32_t sb = (uint32_t)__cvta_generic_to_shared(smem);
    const int tid = threadIdx.x;
    const int lane = tid & 31;
    const int warp = tid >> 5;
    const int wm = warp >> 1;
    const int wn = warp & 1;
    const int m0 = blockIdx.y * 128;
    const int n0 = blockIdx.x * 128;

    Ah += (size_t)blockIdx.z * zA;
    if (SEGS == 2) Al += (size_t)blockIdx.z * zA;
    B  += (size_t)blockIdx.z * zB;
    if (C)  C  += (size_t)blockIdx.z * zC;
    if (Ch) Ch += (size_t)blockIdx.z * zC;
    if (Cl) Cl += (size_t)blockIdx.z * zC;

    const int NCH = Kfull >> 6;

    float acc[2][8][4];
#pragma unroll
    for (int mi = 0; mi < 2; mi++)
#pragma unroll
        for (int ni = 0; ni < 8; ni++)
#pragma unroll
            for (int q = 0; q < 4; q++) acc[mi][ni][q] = 0.f;

    auto load_chunk = [&](int c, int stage) {
        const int kb = c << 6;
        const uint32_t base = sb + stage * STB;
#pragma unroll
        for (int j = 0; j < 4; j++) {
            const int idx = tid + j * 256;
            const int r = idx >> 3, cs = idx & 7;
            const uint32_t soff = (uint32_t)(r * ROWP + cs * 8) * 2;
            const size_t goff = (size_t)r * Kfull + kb + cs * 8;
            cp_async16(base + soff, Ah + (size_t)m0 * Kfull + goff);
            if (SEGS == 2)
                cp_async16(base + TILE_B + soff, Al + (size_t)m0 * Kfull + goff);
            cp_async16(base + SEGS * TILE_B + soff, B + (size_t)n0 * Kfull + goff);
        }
    };

#pragma unroll
    for (int s = 0; s < GSTAGES - 1; s++) {
        if (s < NCH) load_chunk(s, s);
        cp_commit();
    }

    const int la_i = lane & 7;
    const int la_g = lane >> 3;
    const int a_rowadd = la_i + ((la_g & 1) << 3);
    const int a_coladd = (la_g >> 1) << 3;
    const int b_rowadd = la_i + ((la_g >> 1) << 3);
    const int b_coladd = (la_g & 1) << 3;

    for (int c = 0; c < NCH; c++) {
        const int stage = c % GSTAGES;
        cp_wait_group<GSTAGES - 2>();
        __syncthreads();

        const int nc = c + GSTAGES - 1;
        if (nc < NCH) load_chunk(nc, nc % GSTAGES);
        cp_commit();

        const uint32_t base = sb + stage * STB;
        const uint32_t Bbase = base + SEGS * TILE_B;

#pragma unroll
        for (int k16 = 0; k16 < 64; k16 += 16) {
            uint32_t bf[4][4];
#pragma unroll
            for (int nb = 0; nb < 4; nb++) {
                const int row = wn * 64 + nb * 16 + b_rowadd;
                const int col = k16 + b_coladd;
                ldmatrix_x4(bf[nb], Bbase + (uint32_t)(row * ROWP + col) * 2);
            }
#pragma unroll
            for (int seg = 0; seg < SEGS; seg++) {
                const uint32_t Abase = base + seg * TILE_B;
                uint32_t af[2][4];
#pragma unroll
                for (int mi = 0; mi < 2; mi++) {
                    const int row = wm * 32 + mi * 16 + a_rowadd;
                    const int col = k16 + a_coladd;
                    ldmatrix_x4(af[mi], Abase + (uint32_t)(row * ROWP + col) * 2);
                }
#pragma unroll
                for (int nb = 0; nb < 4; nb++)
#pragma unroll
                    for (int mi = 0; mi < 2; mi++) {
                        mma_f16(acc[mi][nb * 2 + 0], af[mi], bf[nb][0], bf[nb][1]);
                        mma_f16(acc[mi][nb * 2 + 1], af[mi], bf[nb][2], bf[nb][3]);
                    }
            }
        }
    }

    const int tq = lane >> 2;
    const int tr = lane & 3;
#pragma unroll
    for (int mi = 0; mi < 2; mi++) {
        const int row = m0 + wm * 32 + mi * 16 + tq;
#pragma unroll
        for (int ni = 0; ni < 8; ni++) {
            const int col = n0 + wn * 64 + ni * 8 + tr * 2;
            const float b0 = bias[col], b1 = bias[col + 1];
            float c00 = acc[mi][ni][0] + b0, c01 = acc[mi][ni][1] + b1;
            float c10 = acc[mi][ni][2] + b0, c11 = acc[mi][ni][3] + b1;
            if (C) {
                float2 v0; v0.x = c00; v0.y = c01;
                float2 v1; v1.x = c10; v1.y = c11;
                *(float2*)&C[(size_t)row * Nfull + col] = v0;
                *(float2*)&C[(size_t)(row + 8) * Nfull + col] = v1;
            }
            if (Ch || Cl) {
                __half h00 = __float2half_rn(c00);
                __half h01 = __float2half_rn(c01);
                __half h10 = __float2half_rn(c10);
                __half h11 = __float2half_rn(c11);
                if (Ch) {
                    *(__half2*)&Ch[(size_t)row * Nfull + col]       = __halves2half2(h00, h01);
                    *(__half2*)&Ch[(size_t)(row + 8) * Nfull + col] = __halves2half2(h10, h11);
                }
                if (Cl) {
                    __half l00 = __float2half_rn(c00 - __half2float(h00));
                    __half l01 = __float2half_rn(c01 - __half2float(h01));
                    __half l10 = __float2half_rn(c10 - __half2float(h10));
                    __half l11 = __float2half_rn(c11 - __half2float(h11));
                    *(__half2*)&Cl[(size_t)row * Nfull + col]       = __halves2half2(l00, l01);
                    *(__half2*)&Cl[(size_t)(row + 8) * Nfull + col] = __halves2half2(l10, l11);
                }
            }
        }
    }
}

// ---------------------------------------------------------------------------
// Split-K selection GEMM via mma.sync (validated k-chunk 32 form)
// ---------------------------------------------------------------------------
#define ROWPAD  40
#define TILE_BYTES (128 * ROWPAD * 2)      // 10240

__global__ __launch_bounds__(256, 2)
void gemm_sel_mma(const __half* __restrict__ SCTh, const __half* __restrict__ SCTl,
                  const __half* __restrict__ CTh, float* __restrict__ S1)
{
    constexpr int STB = 3 * TILE_BYTES;

    extern __shared__ char smem[];
    const uint32_t sb = (uint32_t)__cvta_generic_to_shared(smem);
    const int tid = threadIdx.x;
    const int lane = tid & 31;
    const int warp = tid >> 5;
    const int wm = warp >> 1;
    const int wn = warp & 1;
    const int m0 = blockIdx.y * 128;
    const int n0 = blockIdx.x * 128;
    const int b  = blockIdx.z / SPLITK_SEL;
    const int sl = blockIdx.z % SPLITK_SEL;
    const int kbeg = sl * (MTOK_B / SPLITK_SEL);
    const int NCH = (MTOK_B / SPLITK_SEL) >> 5;

    const __half* Ah = SCTh + (size_t)b * KSEL * MTOK_B;
    const __half* Al = SCTl + (size_t)b * KSEL * MTOK_B;
    const __half* B  = CTh  + (size_t)b * E_DIM * MTOK_B;
    float* C = S1 + (size_t)b * KSEL * E_DIM;

    const int lr0 = tid >> 1;
    const int ls0 = (tid & 1) << 1;

    float acc[2][8][4];
#pragma unroll
    for (int mi = 0; mi < 2; mi++)
#pragma unroll
        for (int ni = 0; ni < 8; ni++)
#pragma unroll
            for (int q = 0; q < 4; q++) acc[mi][ni][q] = 0.f;

    auto load_chunk = [&](int c, int stage) {
        const int kb = kbeg + (c << 5);
        const uint32_t base = sb + stage * STB;
#pragma unroll
        for (int j = 0; j < 2; j++) {
            const int s4 = ls0 + j;
            const uint32_t soff = (uint32_t)(lr0 * ROWPAD + s4 * 8) * 2;
            cp_async16(base + soff,
                       Ah + (size_t)(m0 + lr0) * MTOK_B + kb + s4 * 8);
            cp_async16(base + TILE_BYTES + soff,
                       Al + (size_t)(m0 + lr0) * MTOK_B + kb + s4 * 8);
            cp_async16(base + 2 * TILE_BYTES + soff,
                       B + (size_t)(n0 + lr0) * MTOK_B + kb + s4 * 8);
        }
    };

#pragma unroll
    for (int s = 0; s < GSTAGES - 1; s++) {
        if (s < NCH) load_chunk(s, s);
        cp_commit();
    }

    const int la_i = lane & 7;
    const int la_g = lane >> 3;
    const int a_rowadd = la_i + ((la_g & 1) << 3);
    const int a_coladd = (la_g >> 1) << 3;
    const int b_rowadd = la_i + ((la_g >> 1) << 3);
    const int b_coladd = (la_g & 1) << 3;

    for (int c = 0; c < NCH; c++) {
        const int stage = c % GSTAGES;
        cp_wait_group<GSTAGES - 2>();
        __syncthreads();

        const int nc = c + GSTAGES - 1;
        if (nc < NCH) load_chunk(nc, nc % GSTAGES);
        cp_commit();

        const uint32_t base = sb + stage * STB;
        const uint32_t Bbase = base + 2 * TILE_BYTES;

#pragma unroll
        for (int k16 = 0; k16 < 32; k16 += 16) {
            uint32_t bf[4][4];
#pragma unroll
            for (int nb = 0; nb < 4; nb++) {
                const int row = wn * 64 + nb * 16 + b_rowadd;
                const int col = k16 + b_coladd;
                ldmatrix_x4(bf[nb], Bbase + (uint32_t)(row * ROWPAD + col) * 2);
            }
#pragma unroll
            for (int seg = 0; seg < 2; seg++) {
                const uint32_t Abase = base + seg * TILE_BYTES;
                uint32_t af[2][4];
#pragma unroll
                for (int mi = 0; mi < 2; mi++) {
                    const int row = wm * 32 + mi * 16 + a_rowadd;
                    const int col = k16 + a_coladd;
                    ldmatrix_x4(af[mi], Abase + (uint32_t)(row * ROWPAD + col) * 2);
                }
#pragma unroll
                for (int nb = 0; nb < 4; nb++)
#pragma unroll
                    for (int mi = 0; mi < 2; mi++) {
                        mma_f16(acc[mi][nb * 2 + 0], af[mi], bf[nb][0], bf[nb][1]);
                        mma_f16(acc[mi][nb * 2 + 1], af[mi], bf[nb][2], bf[nb][3]);
                    }
            }
        }
    }

    const int tq = lane >> 2;
    const int tr = lane & 3;
#pragma unroll
    for (int mi = 0; mi < 2; mi++) {
        const int row = m0 + wm * 32 + mi * 16 + tq;
#pragma unroll
        for (int ni = 0; ni < 8; ni++) {
            const int col = n0 + wn * 64 + ni * 8 + tr * 2;
            atomicAdd(&C[(size_t)row * E_DIM + col],           acc[mi][ni][0]);
            atomicAdd(&C[(size_t)row * E_DIM + col + 1],       acc[mi][ni][1]);
            atomicAdd(&C[(size_t)(row + 8) * E_DIM + col],     acc[mi][ni][2]);
            atomicAdd(&C[(size_t)(row + 8) * E_DIM + col + 1], acc[mi][ni][3]);
        }
    }
}

// ---------------------------------------------------------------------------
// mma.sync spatial attention (S=256, step 1), flash-style online softmax.
// ---------------------------------------------------------------------------
#define AKS_BYTES  (256 * 72 * 2)
#define AVT_BYTES  (64 * 264 * 2)
#define ATTN_SMEM  (AKS_BYTES + AVT_BYTES + 512 * 4)   // 74704

__global__ __launch_bounds__(256)
void attn_mma(const __half* __restrict__ Q, const __half* __restrict__ K,
              const __half* __restrict__ V,
              __half* __restrict__ OutH,
              const float* __restrict__ rb, int ldx)
{
    const int h = blockIdx.x;
    const int g = blockIdx.y;
    const int qh = blockIdx.z;
    const int base_m = g * N_DIM;
    const size_t baseE = (size_t)base_m * ldx + h * D_DIM;

    extern __shared__ char sm8[];
    __half* Ks = (__half*)sm8;
    __half* Vt = (__half*)(sm8 + AKS_BYTES);
    float*  rbh = (float*)(sm8 + AKS_BYTES + AVT_BYTES);
    const uint32_t sKs = (uint32_t)__cvta_generic_to_shared(Ks);
    const uint32_t sVt = (uint32_t)__cvta_generic_to_shared(Vt);

    const int tid = threadIdx.x;
    const int lane = tid & 31;
    const int warp = tid >> 5;

    for (int i = tid; i < 128 * 8; i += 256) {
        int r = i >> 3, cs = i & 7;
        *(float4*)&Ks[r * 72 + cs * 8] =
            *(const float4*)(Q + baseE + (size_t)(qh * 128 + r) * ldx + cs * 8);
    }
    __syncthreads();

    const int la_i = lane & 7;
    const int la_g = lane >> 3;
    const int a_rowadd = la_i + ((la_g & 1) << 3);
    const int a_coladd = (la_g >> 1) << 3;
    const int b_rowadd = la_i + ((la_g >> 1) << 3);
    const int b_coladd = (la_g & 1) << 3;

    uint32_t Qf[4][4];
    const int wq = warp * 16;
#pragma unroll
    for (int kk = 0; kk < 4; kk++)
        ldmatrix_x4(Qf[kk], sKs + (uint32_t)((wq + a_rowadd) * 72 + kk * 16 + a_coladd) * 2);
    __syncthreads();

    for (int i = tid; i < 256 * 8; i += 256) {
        int r = i >> 3, cs = i & 7;
        *(float4*)&Ks[r * 72 + cs * 8] =
            *(const float4*)(K + baseE + (size_t)r * ldx + cs * 8);
    }
    for (int i = tid; i < 256 * 32; i += 256) {
        int t = i >> 5, d2 = i & 31;
        __half2 v = *(const __half2*)(V + baseE + (size_t)t * ldx + 2 * d2);
        Vt[(2 * d2) * 264 + t]     = __low2half(v);
        Vt[(2 * d2 + 1) * 264 + t] = __high2half(v);
    }
    for (int i = tid; i < 511; i += 256)
        rbh[i] = rb[(size_t)(MAXLEN - 256 + i) * H_DIM + h];
    __syncthreads();

    const int tq = lane >> 2;
    const int tr = lane & 3;
    const int r0 = qh * 128 + wq + tq;
    const int r1 = r0 + 8;

    float o[8][4];
#pragma unroll
    for (int j = 0; j < 8; j++)
#pragma unroll
        for (int q = 0; q < 4; q++) o[j][q] = 0.f;
    float m0 = -1e30f, m1 = -1e30f, l0 = 0.f, l1 = 0.f;

#pragma unroll
    for (int ch = 0; ch < 4; ch++) {
        float s[8][4];
#pragma unroll
        for (int j = 0; j < 8; j++)
#pragma unroll
            for (int q = 0; q < 4; q++) s[j][q] = 0.f;

#pragma unroll
        for (int kk = 0; kk < 4; kk++) {
#pragma unroll
            for (int nb = 0; nb < 4; nb++) {
                uint32_t bf[4];
                ldmatrix_x4(bf, sKs + (uint32_t)((ch * 64 + nb * 16 + b_rowadd) * 72
                                                 + kk * 16 + b_coladd) * 2);
                mma_f16(s[nb * 2 + 0], Qf[kk], bf[0], bf[1]);
                mma_f16(s[nb * 2 + 1], Qf[kk], bf[2], bf[3]);
            }
        }

        float cm0 = -1e30f, cm1 = -1e30f;
#pragma unroll
        for (int j = 0; j < 8; j++) {
            const int c = ch * 64 + j * 8 + 2 * tr;
            s[j][0] = s[j][0] * 0.125f + rbh[c - r0 + 255];
            s[j][1] = s[j][1] * 0.125f + rbh[c + 1 - r0 + 255];
            s[j][2] = s[j][2] * 0.125f + rbh[c - r1 + 255];
            s[j][3] = s[j][3] * 0.125f + rbh[c + 1 - r1 + 255];
            cm0 = fmaxf(cm0, fmaxf(s[j][0], s[j][1]));
            cm1 = fmaxf(cm1, fmaxf(s[j][2], s[j][3]));
        }
        cm0 = fmaxf(cm0, __shfl_xor_sync(0xffffffffu, cm0, 1));
        cm0 = fmaxf(cm0, __shfl_xor_sync(0xffffffffu, cm0, 2));
        cm1 = fmaxf(cm1, __shfl_xor_sync(0xffffffffu, cm1, 1));
        cm1 = fmaxf(cm1, __shfl_xor_sync(0xffffffffu, cm1, 2));

        const float nm0 = fmaxf(m0, cm0), nm1 = fmaxf(m1, cm1);
        const float sc0 = __expf(m0 - nm0), sc1 = __expf(m1 - nm1);
        float rs0 = 0.f, rs1 = 0.f;
#pragma unroll
        for (int j = 0; j < 8; j++) {
            s[j][0] = __expf(s[j][0] - nm0);
            s[j][1] = __expf(s[j][1] - nm0);
            s[j][2] = __expf(s[j][2] - nm1);
            s[j][3] = __expf(s[j][3] - nm1);
            rs0 += s[j][0] + s[j][1];
            rs1 += s[j][2] + s[j][3];
        }
        rs0 += __shfl_xor_sync(0xffffffffu, rs0, 1);
        rs0 += __shfl_xor_sync(0xffffffffu, rs0, 2);
        rs1 += __shfl_xor_sync(0xffffffffu, rs1, 1);
        rs1 += __shfl_xor_sync(0xffffffffu, rs1, 2);
        l0 = l0 * sc0 + rs0;
        l1 = l1 * sc1 + rs1;
        m0 = nm0; m1 = nm1;
#pragma unroll
        for (int j = 0; j < 8; j++) {
            o[j][0] *= sc0; o[j][1] *= sc0;
            o[j][2] *= sc1; o[j][3] *= sc1;
        }

        uint32_t pa[4][4];
#pragma unroll
        for (int kk = 0; kk < 4; kk++) {
            pa[kk][0] = h2pack(s[2 * kk][0], s[2 * kk][1]);
            pa[kk][1] = h2pack(s[2 * kk][2], s[2 * kk][3]);
            pa[kk][2] = h2pack(s[2 * kk + 1][0], s[2 * kk + 1][1]);
            pa[kk][3] = h2pack(s[2 * kk + 1][2], s[2 * kk + 1][3]);
        }

#pragma unroll
        for (int kk = 0; kk < 4; kk++) {
#pragma unroll
            for (int nb = 0; nb < 4; nb++) {
                uint32_t bf[4];
                ldmatrix_x4(bf, sVt + (uint32_t)((nb * 16 + b_rowadd) * 264
                                                 + ch * 64 + kk * 16 + b_coladd) * 2);
                mma_f16(o[nb * 2 + 0], pa[kk], bf[0], bf[1]);
                mma_f16(o[nb * 2 + 1], pa[kk], bf[2], bf[3]);
            }
        }
    }

    const float inv0 = 1.f / l0, inv1 = 1.f / l1;
    const size_t oo0 = (size_t)(base_m + r0) * E_DIM + h * D_DIM;
    const size_t oo1 = (size_t)(base_m + r1) * E_DIM + h * D_DIM;
#pragma unroll
    for (int j = 0; j < 8; j++) {
        const int c = j * 8 + 2 * tr;
        *(__half2*)&OutH[oo0 + c] =
            __floats2half2_rn(o[j][0] * inv0, o[j][1] * inv0);
        *(__half2*)&OutH[oo1 + c] =
            __floats2half2_rn(o[j][2] * inv1, o[j][3] * inv1);
    }
}

// ---------------------------------------------------------------------------
// mma.sync temporal attention (S=32, step N_DIM): one warp per (h,b,n) group.
// ---------------------------------------------------------------------------
#define TBUF_HALVES 2560
#define ATTN_T_SMEM (8 * TBUF_HALVES * 2 + 64 * 4)   // 41216

__global__ __launch_bounds__(256)
void attn_mma_t(const __half* __restrict__ Q, const __half* __restrict__ K,
                const __half* __restrict__ V,
                __half* __restrict__ OutH,
                const float* __restrict__ rb, int ldx)
{
    const int h = blockIdx.x;
    const int tid = threadIdx.x;
    const int lane = tid & 31;
    const int warp = tid >> 5;
    const int g = blockIdx.y * 8 + warp;
    const int b = g >> 8, n = g & 255;
    const int base_m = b * MTOK_B + n;
    const size_t baseE = (size_t)base_m * ldx + h * D_DIM;
    const size_t stepE = (size_t)N_DIM * ldx;

    extern __shared__ char smT[];
    __half* buf = (__half*)smT + warp * TBUF_HALVES;
    float* rbh = (float*)(smT + 8 * TBUF_HALVES * 2);
    const uint32_t sb = (uint32_t)__cvta_generic_to_shared(buf);

    for (int i = tid; i < 63; i += 256)
        rbh[i] = rb[(size_t)(MAXLEN - 32 + i) * H_DIM + h];
    __syncthreads();

    const int la_i = lane & 7;
    const int la_g = lane >> 3;
    const int a_rowadd = la_i + ((la_g & 1) << 3);
    const int a_coladd = (la_g >> 1) << 3;
    const int b_rowadd = la_i + ((la_g >> 1) << 3);
    const int b_coladd = (la_g & 1) << 3;
    const int tq = lane >> 2;
    const int tr = lane & 3;

#pragma unroll
    for (int j = 0; j < 8; j++) {
        int idx = lane + j * 32;
        int r = idx >> 3, cs = idx & 7;
        *(float4*)&buf[r * 72 + cs * 8] =
            *(const float4*)(Q + baseE + (size_t)r * stepE + cs * 8);
    }
    __syncwarp();
    uint32_t Qf[2][4][4];
#pragma unroll
    for (int mi = 0; mi < 2; mi++)
#pragma unroll
        for (int kk = 0; kk < 4; kk++)
            ldmatrix_x4(Qf[mi][kk],
                        sb + (uint32_t)((mi * 16 + a_rowadd) * 72 + kk * 16 + a_coladd) * 2);
    __syncwarp();

#pragma unroll
    for (int j = 0; j < 8; j++) {
        int idx = lane + j * 32;
        int r = idx >> 3, cs = idx & 7;
        *(float4*)&buf[r * 72 + cs * 8] =
            *(const float4*)(K + baseE + (size_t)r * stepE + cs * 8);
    }
    __syncwarp();

    float s[2][4][4];
#pragma unroll
    for (int mi = 0; mi < 2; mi++)
#pragma unroll
        for (int ni = 0; ni < 4; ni++)
#pragma unroll
            for (int q = 0; q < 4; q++) s[mi][ni][q] = 0.f;

#pragma unroll
    for (int kk = 0; kk < 4; kk++)
#pragma unroll
        for (int nb = 0; nb < 2; nb++) {
            uint32_t bf[4];
            ldmatrix_x4(bf, sb + (uint32_t)((nb * 16 + b_rowadd) * 72 + kk * 16 + b_coladd) * 2);
#pragma unroll
            for (int mi = 0; mi < 2; mi++) {
                mma_f16(s[mi][nb * 2 + 0], Qf[mi][kk], bf[0], bf[1]);
                mma_f16(s[mi][nb * 2 + 1], Qf[mi][kk], bf[2], bf[3]);
            }
        }
    __syncwarp();

#pragma unroll
    for (int j = 0; j < 32; j++) {
        __half2 v = *(const __half2*)(V + baseE + (size_t)j * stepE + 2 * lane);
        buf[(2 * lane) * 40 + j]     = __low2half(v);
        buf[(2 * lane + 1) * 40 + j] = __high2half(v);
    }
    __syncwarp();

#pragma unroll
    for (int mi = 0; mi < 2; mi++) {
        const int ra = mi * 16 + tq, rb2 = ra + 8;
        float mxa = -1e30f, mxb = -1e30f;
#pragma unroll
        for (int ni = 0; ni < 4; ni++) {
            const int c = ni * 8 + 2 * tr;
            s[mi][ni][0] = s[mi][ni][0] * 0.125f + rbh[c - ra + 31];
            s[mi][ni][1] = s[mi][ni][1] * 0.125f + rbh[c + 1 - ra + 31];
            s[mi][ni][2] = s[mi][ni][2] * 0.125f + rbh[c - rb2 + 31];
            s[mi][ni][3] = s[mi][ni][3] * 0.125f + rbh[c + 1 - rb2 + 31];
            mxa = fmaxf(mxa, fmaxf(s[mi][ni][0], s[mi][ni][1]));
            mxb = fmaxf(mxb, fmaxf(s[mi][ni][2], s[mi][ni][3]));
        }
        mxa = fmaxf(mxa, __shfl_xor_sync(0xffffffffu, mxa, 1));
        mxa = fmaxf(mxa, __shfl_xor_sync(0xffffffffu, mxa, 2));
        mxb = fmaxf(mxb, __shfl_xor_sync(0xffffffffu, mxb, 1));
        mxb = fmaxf(mxb, __shfl_xor_sync(0xffffffffu, mxb, 2));
        float sa = 0.f, sbm = 0.f;
#pragma unroll
        for (int ni = 0; ni < 4; ni++) {
            s[mi][ni][0] = __expf(s[mi][ni][0] - mxa);
            s[mi][ni][1] = __expf(s[mi][ni][1] - mxa);
            s[mi][ni][2] = __expf(s[mi][ni][2] - mxb);
            s[mi][ni][3] = __expf(s[mi][ni][3] - mxb);
            sa += s[mi][ni][0] + s[mi][ni][1];
            sbm += s[mi][ni][2] + s[mi][ni][3];
        }
        sa += __shfl_xor_sync(0xffffffffu, sa, 1);
        sa += __shfl_xor_sync(0xffffffffu, sa, 2);
        sbm += __shfl_xor_sync(0xffffffffu, sbm, 1);
        sbm += __shfl_xor_sync(0xffffffffu, sbm, 2);
        const float ia = 1.f / sa, ib = 1.f / sbm;
#pragma unroll
        for (int ni = 0; ni < 4; ni++) {
            s[mi][ni][0] *= ia; s[mi][ni][1] *= ia;
            s[mi][ni][2] *= ib; s[mi][ni][3] *= ib;
        }
    }

    uint32_t pa[2][2][4];
#pragma unroll
    for (int mi = 0; mi < 2; mi++)
#pragma unroll
        for (int kk = 0; kk < 2; kk++) {
            pa[mi][kk][0] = h2pack(s[mi][2 * kk][0], s[mi][2 * kk][1]);
            pa[mi][kk][1] = h2pack(s[mi][2 * kk][2], s[mi][2 * kk][3]);
            pa[mi][kk][2] = h2pack(s[mi][2 * kk + 1][0], s[mi][2 * kk + 1][1]);
            pa[mi][kk][3] = h2pack(s[mi][2 * kk + 1][2], s[mi][2 * kk + 1][3]);
        }

    float o[2][8][4];
#pragma unroll
    for (int mi = 0; mi < 2; mi++)
#pragma unroll
        for (int ni = 0; ni < 8; ni++)
#pragma unroll
            for (int q = 0; q < 4; q++) o[mi][ni][q] = 0.f;

#pragma unroll
    for (int kk = 0; kk < 2; kk++)
#pragma unroll
        for (int nb = 0; nb < 4; nb++) {
            uint32_t bf[4];
            ldmatrix_x4(bf, sb + (uint32_t)((nb * 16 + b_rowadd) * 40 + kk * 16 + b_coladd) * 2);
#pragma unroll
            for (int mi = 0; mi < 2; mi++) {
                mma_f16(o[mi][nb * 2 + 0], pa[mi][kk], bf[0], bf[1]);
                mma_f16(o[mi][nb * 2 + 1], pa[mi][kk], bf[2], bf[3]);
            }
        }

#pragma unroll
    for (int mi = 0; mi < 2; mi++) {
        const int ra = mi * 16 + tq;
        const size_t oo0 = (size_t)(base_m + ra * N_DIM) * E_DIM + h * D_DIM;
        const size_t oo1 = (size_t)(base_m + (ra + 8) * N_DIM) * E_DIM + h * D_DIM;
#pragma unroll
        for (int ni = 0; ni < 8; ni++) {
            const int c = ni * 8 + 2 * tr;
            *(__half2*)&OutH[oo0 + c] = __floats2half2_rn(o[mi][ni][0], o[mi][ni][1]);
            *(__half2*)&OutH[oo1 + c] = __floats2half2_rn(o[mi][ni][2], o[mi][ni][3]);
        }
    }
}

// ---------------------------------------------------------------------------
// misc elementwise / prep kernels
// ---------------------------------------------------------------------------
__global__ void cvt_hilo(const float* __restrict__ x, __half* __restrict__ hi,
                         __half* __restrict__ lo, int n4)
{
    int i = blockIdx.x * blockDim.x + threadIdx.x;
    if (i >= n4) return;
    float4 v = ((const float4*)x)[i];
    __half h0 = __float2half_rn(v.x);
    __half h1 = __float2half_rn(v.y);
    __half h2 = __float2half_rn(v.z);
    __half h3 = __float2half_rn(v.w);
    __half l0 = __float2half_rn(v.x - __half2float(h0));
    __half l1 = __float2half_rn(v.y - __half2float(h1));
    __half l2 = __float2half_rn(v.z - __half2float(h2));
    __half l3 = __float2half_rn(v.w - __half2float(h3));
    __half2* hp = (__half2*)hi;
    __half2* lp = (__half2*)lo;
    hp[2 * i + 0] = __half2(h0, h1);
    hp[2 * i + 1] = __half2(h2, h3);
    lp[2 * i + 0] = __half2(l0, l1);
    lp[2 * i + 1] = __half2(l2, l3);
}

__global__ void cvt_f16(const float* __restrict__ x, __half* __restrict__ y, int n4)
{
    int i = blockIdx.x * blockDim.x + threadIdx.x;
    if (i >= n4) return;
    float4 v = ((const float4*)x)[i];
    __half2* yp = (__half2*)y;
    yp[2 * i + 0] = __floats2half2_rn(v.x, v.y);
    yp[2 * i + 1] = __floats2half2_rn(v.z, v.w);
}

// Weight transpose + fp16 hi/lo convert; z-index offset by zbase.
__global__ void wt_cvt3(const float* __restrict__ W, __half* __restrict__ WTh,
                        __half* __restrict__ WTl, int Kd, int Nd, int type, int slots,
                        int zbase)
{
    __shared__ float t[32][33];
    const int z = blockIdx.z + zbase;
    const size_t srcoff = (size_t)z * Kd * Nd;
    const size_t dstoff = ((size_t)z * slots + type) * Kd * Nd;
    const float* Wm = W + srcoff;
    __half* Hh = WTh + dstoff;
    __half* Hl = WTl + dstoff;

    int nx = blockIdx.x * 32 + threadIdx.x;
    int k0 = blockIdx.y * 32;
#pragma unroll
    for (int j = 0; j < 4; j++) {
        int kk = k0 + threadIdx.y + j * 8;
        t[threadIdx.y + j * 8][threadIdx.x] = Wm[(size_t)kk * Nd + nx];
    }
    __syncthreads();
    int kx = k0 + threadIdx.x;
#pragma unroll
    for (int j = 0; j < 4; j++) {
        int nn = blockIdx.x * 32 + threadIdx.y + j * 8;
        float v = t[threadIdx.x][threadIdx.y + j * 8];
        __half h = __float2half_rn(v);
        Hh[(size_t)nn * Kd + kx] = h;
        Hl[(size_t)nn * Kd + kx] = __float2half_rn(v - __half2float(h));
    }
}

__global__ void wt_cvt(const float* __restrict__ W, __half* __restrict__ WT,
                       int Kd, int Nd)
{
    __shared__ float t[32][33];
    const size_t moff = (size_t)blockIdx.z * Kd * Nd;
    const float* Wm = W + moff;
    __half* Hh = WT + moff;

    int nx = blockIdx.x * 32 + threadIdx.x;
    int k0 = blockIdx.y * 32;
#pragma unroll
    for (int j = 0; j < 4; j++) {
        int kk = k0 + threadIdx.y + j * 8;
        t[threadIdx.y + j * 8][threadIdx.x] = Wm[(size_t)kk * Nd + nx];
    }
    __syncthreads();
    int kx = k0 + threadIdx.x;
#pragma unroll
    for (int j = 0; j < 4; j++) {
        int nn = blockIdx.x * 32 + threadIdx.y + j * 8;
        Hh[(size_t)nn * Kd + kx] = __float2half_rn(t[threadIdx.x][threadIdx.y + j * 8]);
    }
}

// transpose + hi/lo split: src fp32 [z][R][C] -> dst fp16 [z][C][R]
__global__ void transp_hilo(const float* __restrict__ src, __half* __restrict__ dh,
                            __half* __restrict__ dl, int R, int C)
{
    __shared__ float t[32][33];
    const size_t zo = (size_t)blockIdx.z * R * C;
    const float* S = src + zo;
    __half* Dh = dh + zo;
    __half* Dl = dl ? dl + zo : nullptr;

    int cx = blockIdx.x * 32 + threadIdx.x;
    int r0 = blockIdx.y * 32;
#pragma unroll
    for (int j = 0; j < 4; j++) {
        int rr = r0 + threadIdx.y + j * 8;
        t[threadIdx.y + j * 8][threadIdx.x] = S[(size_t)rr * C + cx];
    }
    __syncthreads();
    int rx = r0 + threadIdx.x;
#pragma unroll
    for (int j = 0; j < 4; j++) {
        int cc = blockIdx.x * 32 + threadIdx.y + j * 8;
        float v = t[threadIdx.x][threadIdx.y + j * 8];
        __half h = __float2half_rn(v);
        Dh[(size_t)cc * R + rx] = h;
        if (Dl) Dl[(size_t)cc * R + rx] = __float2half_rn(v - __half2float(h));
    }
}

// fp16 transpose: src fp16 [z][R][C] -> dst fp16 [z][C][R]
__global__ void transp_h16(const __half* __restrict__ src, __half* __restrict__ dst,
                           int R, int C)
{
    __shared__ __half t[32][33];
    const size_t zo = (size_t)blockIdx.z * R * C;
    const __half* S = src + zo;
    __half* D = dst + zo;

    int cx = blockIdx.x * 32 + threadIdx.x;
    int r0 = blockIdx.y * 32;
#pragma unroll
    for (int j = 0; j < 4; j++) {
        int rr = r0 + threadIdx.y + j * 8;
        t[threadIdx.y + j * 8][threadIdx.x] = S[(size_t)rr * C + cx];
    }
    __syncthreads();
    int rx = r0 + threadIdx.x;
#pragma unroll
    for (int j = 0; j < 4; j++) {
        int cc = blockIdx.x * 32 + threadIdx.y + j * 8;
        D[(size_t)cc * R + rx] = t[threadIdx.x][threadIdx.y + j * 8];
    }
}

__global__ void bias_concat(const float* __restrict__ bq, const float* __restrict__ bk,
                            const float* __restrict__ bv, float* __restrict__ out)
{
    int i = blockIdx.x * blockDim.x + threadIdx.x;
    if (i >= 4 * QKV_N) return;
    int a = i / QKV_N;
    int r = i % QKV_N;
    const float* src = (r < E_DIM) ? bq : (r < 2 * E_DIM) ? bk : bv;
    out[i] = src[a * E_DIM + (r & (E_DIM - 1))];
}

__global__ void bias_comb(const float* __restrict__ wq, const float* __restrict__ wk,
                          const float* __restrict__ wv, const float* __restrict__ bd,
                          const float* __restrict__ bqkv, float* __restrict__ out)
{
    int i = blockIdx.x * blockDim.x + threadIdx.x;
    int z = blockIdx.y;
    const float* W = (i < E_DIM) ? wq : (i < 2 * E_DIM) ? wk : wv;
    int col = i & (E_DIM - 1);
    const float* Wm = W + (size_t)(z + 1) * E_DIM * E_DIM;
    const float* bdz = bd + (size_t)z * E_DIM;
    float s = 0.f;
    for (int k = 0; k < E_DIM; k++)
        s += bdz[k] * Wm[(size_t)k * E_DIM + col];
    out[(size_t)z * QKV_N + i] = s + bqkv[(size_t)(z + 1) * QKV_N + i];
}

__global__ void bias_sel(const float* __restrict__ selw, const float* __restrict__ selb,
                         const float* __restrict__ bd3, float* __restrict__ out)
{
    int k = blockIdx.x * blockDim.x + threadIdx.x;
    if (k >= KSEL) return;
    float s = 0.f;
    for (int e = 0; e < E_DIM; e++)
        s += bd3[e] * selw[(size_t)e * KSEL + k];
    out[k] = s + selb[k];
}

// ---------------------------------------------------------------------------
// Selection softmax / pooling
// ---------------------------------------------------------------------------
__global__ __launch_bounds__(256)
void sel_softmax(float* __restrict__ sc)
{
    const int b = blockIdx.x;
    const int k0 = blockIdx.y * 32;
    const int lane = threadIdx.x & 31;
    const int row = threadIdx.x >> 5;

    float* base = sc + (size_t)b * MTOK_B * KSEL + k0 + lane;

    __shared__ float redA[8][32];
    __shared__ float redB[8][32];

    float mx = -1e30f;
    for (int m = row; m < MTOK_B; m += 8)
        mx = fmaxf(mx, base[(size_t)m * KSEL]);
    redA[row][lane] = mx;
    __syncthreads();
    if (row == 0) {
        float v = redA[0][lane];
#pragma unroll
        for (int r = 1; r < 8; r++) v = fmaxf(v, redA[r][lane]);
        redA[0][lane] = v;
    }
    __syncthreads();
    mx = redA[0][lane];

    float sum = 0.f;
    for (int m = row; m < MTOK_B; m += 8)
        sum += __expf(base[(size_t)m * KSEL] - mx);
    redB[row][lane] = sum;
    __syncthreads();
    if (row == 0) {
        float v = 0.f;
#pragma unroll
        for (int r = 0; r < 8; r++) v += redB[r][lane];
        redB[0][lane] = v;
    }
    __syncthreads();
    float inv = 1.f / redB[0][lane];

    for (int m = row; m < MTOK_B; m += 8) {
        float* p = &base[(size_t)m * KSEL];
        *p = __expf(*p - mx) * inv;
    }
}

__global__ void pool_kernel(const float* __restrict__ sel, float* __restrict__ out)
{
    int idx = blockIdx.x * blockDim.x + threadIdx.x;
    int total = B_DIM * OUT_ROWS * E_DIM;
    if (idx >= total) return;
    int e = idx % E_DIM;
    int r = (idx / E_DIM) % OUT_ROWS;
    int b = idx / (OUT_ROWS * E_DIM);
    const float* sb = sel + (size_t)b * KSEL * E_DIM;
    float v;
    if (r < 256) {
        v = sb[(size_t)r * E_DIM + e];
    } else if (r < 384) {
        int i = (r - 256) * 2;
        v = 0.5f * (sb[(size_t)i * E_DIM + e] + sb[(size_t)(i + 1) * E_DIM + e]);
    } else {
        int i = (r - 384) * 4;
        v = 0.25f * (sb[(size_t)i * E_DIM + e] + sb[(size_t)(i + 1) * E_DIM + e] +
                     sb[(size_t)(i + 2) * E_DIM + e] + sb[(size_t)(i + 3) * E_DIM + e]);
    }
    out[idx] = v;
}

// ---------------------------------------------------------------------------
// Orchestration (R15 weight-prep placement + safe R16 wins)
// ---------------------------------------------------------------------------
extern "C" void kernel_launch(void* const* d_in, const int* in_sizes, int n_in,
                              void* d_out, int out_size)
{
    (void)in_sizes; (void)n_in; (void)out_size;

    const float* x    = (const float*)d_in[0];
    const float* wq   = (const float*)d_in[1];
    const float* bq   = (const float*)d_in[2];
    const float* wk   = (const float*)d_in[3];
    const float* bk   = (const float*)d_in[4];
    const float* wv   = (const float*)d_in[5];
    const float* bv   = (const float*)d_in[6];
    const float* wd   = (const float*)d_in[7];
    const float* bd   = (const float*)d_in[8];
    const float* rb   = (const float*)d_in[9];
    const float* selw = (const float*)d_in[10];
    const float* selb = (const float*)d_in[11];
    float* out = (float*)d_out;

    float *SCb, *S1b, *SELb, *Bqkv, *Bcomb, *Bias2, *Bzero;
    cudaGetSymbolAddress((void**)&SCb, g_SC);
    cudaGetSymbolAddress((void**)&S1b, g_S1);
    cudaGetSymbolAddress((void**)&SELb, g_SEL);
    cudaGetSymbolAddress((void**)&Bqkv, g_Bqkv);
    cudaGetSymbolAddress((void**)&Bcomb, g_Bcomb);
    cudaGetSymbolAddress((void**)&Bias2, g_Bias2);
    cudaGetSymbolAddress((void**)&Bzero, g_Bzero);

    __half *QKVh, *Ahp, *Ah2p, *Al2p, *WqkvTh, *WqkvTl, *Wd16, *WdT3, *WcT;
    __half *SWTh, *SWTl, *Bsel, *SCTh, *SCTl, *CTh;
    cudaGetSymbolAddress((void**)&QKVh, g_QKVh);
    cudaGetSymbolAddress((void**)&Ahp, g_Ah);
    cudaGetSymbolAddress((void**)&Ah2p, g_Ah2);
    cudaGetSymbolAddress((void**)&Al2p, g_Al2);
    cudaGetSymbolAddress((void**)&WqkvTh, g_WqkvTh);
    cudaGetSymbolAddress((void**)&WqkvTl, g_WqkvTl);
    cudaGetSymbolAddress((void**)&Wd16, g_Wd16);
    cudaGetSymbolAddress((void**)&WdT3, g_WdT3);
    cudaGetSymbolAddress((void**)&WcT, g_WcT);
    cudaGetSymbolAddress((void**)&SWTh, g_SWTh);
    cudaGetSymbolAddress((void**)&SWTl, g_SWTl);
    cudaGetSymbolAddress((void**)&Bsel, g_Bsel);
    cudaGetSymbolAddress((void**)&SCTh, g_SCTh);
    cudaGetSymbolAddress((void**)&SCTl, g_SCTl);
    cudaGetSymbolAddress((void**)&CTh, g_CTh);

    static cudaStream_t s2 = nullptr;
    static cudaEvent_t evF = nullptr, evJ = nullptr, evA = nullptr, evT = nullptr;
    if (!s2) {
        cudaStreamCreateWithFlags(&s2, cudaStreamNonBlocking);
        cudaEventCreateWithFlags(&evF, cudaEventDisableTiming);
        cudaEventCreateWithFlags(&evJ, cudaEventDisableTiming);
        cudaEventCreateWithFlags(&evA, cudaEventDisableTiming);
        cudaEventCreateWithFlags(&evT, cudaEventDisableTiming);
    }

    const int SMEM1 = GSTAGES * 2 * TILE_B;    // 110592
    const int SMEM2 = GSTAGES * 3 * TILE_B;    // 165888
    const int SMEM_SEL = GSTAGES * 3 * TILE_BYTES;   // 92160
    cudaFuncSetAttribute((const void*)attn_mma,
                         cudaFuncAttributeMaxDynamicSharedMemorySize, ATTN_SMEM);
    cudaFuncSetAttribute((const void*)attn_mma_t,
                         cudaFuncAttributeMaxDynamicSharedMemorySize, ATTN_T_SMEM);
    cudaFuncSetAttribute((const void*)gemm_f16<1>,
                         cudaFuncAttributeMaxDynamicSharedMemorySize, SMEM1);
    cudaFuncSetAttribute((const void*)gemm_f16<2>,
                         cudaFuncAttributeMaxDynamicSharedMemorySize, SMEM2);
    cudaFuncSetAttribute((const void*)gemm_sel_mma,
                         cudaFuncAttributeMaxDynamicSharedMemorySize, SMEM_SEL);

    const dim3 blk(256);
    const dim3 tblk(32, 8);
    const int n4 = MTOK * E_DIM / 4;
    const dim3 gcvt((n4 + 255) / 256);
    const dim3 gQKV(QKV_N / 128, MTOK / 128);
    const size_t MM = (size_t)E_DIM * E_DIM;
    const size_t MM3 = 3 * MM;
    const size_t WCS = (size_t)QKV_N * E_DIM;

    // ---- main stream: ALL QKV weight conversion up front (R15 placement) ----
    wt_cvt3<<<dim3(E_DIM / 32, E_DIM / 32, 4), tblk>>>(wq, WqkvTh, WqkvTl, E_DIM, E_DIM, 0, 3, 0);
    wt_cvt3<<<dim3(E_DIM / 32, E_DIM / 32, 4), tblk>>>(wk, WqkvTh, WqkvTl, E_DIM, E_DIM, 1, 3, 0);
    wt_cvt3<<<dim3(E_DIM / 32, E_DIM / 32, 4), tblk>>>(wv, WqkvTh, WqkvTl, E_DIM, E_DIM, 2, 3, 0);
    bias_concat<<<(4 * QKV_N + 255) / 256, blk>>>(bq, bk, bv, Bqkv);

    // ---- fork: fold-weight prep on s2 (R11/R15-proven scope) ----
    cudaEventRecord(evF, 0);
    cudaStreamWaitEvent(s2, evF, 0);

    cvt_f16<<<(int)((4 * MM / 4 + 255) / 256), blk, 0, s2>>>(wd, Wd16, (int)(4 * MM / 4));
    gemm_f16<2><<<dim3(E_DIM / 128, QKV_N / 128, 3), blk, SMEM2, s2>>>(
        WqkvTh + MM3, WqkvTl + MM3, Wd16, Bzero, nullptr,
        WcT, nullptr, E_DIM, E_DIM, MM3, MM, WCS);
    wt_cvt<<<dim3(E_DIM / 32, E_DIM / 32, 1), tblk, 0, s2>>>(wd + 3 * MM, WdT3, E_DIM, E_DIM);
    wt_cvt3<<<dim3(KSEL / 32, E_DIM / 32, 1), tblk, 0, s2>>>(selw, SWTh, SWTl, E_DIM, KSEL, 0, 1, 0);
    gemm_f16<2><<<dim3(E_DIM / 128, KSEL / 128), blk, SMEM2, s2>>>(
        SWTh, SWTl, Wd16 + 3 * MM, Bzero, nullptr,
        Bsel, nullptr, E_DIM, E_DIM, 0, 0, 0);
    bias_comb<<<dim3(QKV_N / 256, 3), blk, 0, s2>>>(wq, wk, wv, bd, Bqkv, Bcomb);
    bias_sel<<<1, 256, 0, s2>>>(selw, selb, bd + 3 * E_DIM, Bias2);
    cudaMemsetAsync(S1b, 0, (size_t)B_DIM * KSEL * E_DIM * sizeof(float), s2);
    cudaEventRecord(evJ, s2);

    // ---- main stream: layer 0 (x hi only; lo is dead for SEGS=1 GEMM) ----
    cvt_f16<<<gcvt, blk>>>(x, Ah2p, n4);
    gemm_f16<1><<<gQKV, blk, SMEM1>>>(Ah2p, nullptr, WqkvTh, Bqkv, nullptr,
                                      QKVh, nullptr, QKV_N, E_DIM, 0, 0, 0);
    attn_mma<<<dim3(H_DIM, B_DIM * T_DIM, 2), blk, ATTN_SMEM>>>(
        QKVh, QKVh + E_DIM, QKVh + 2 * E_DIM, Ahp, rb, QKV_N);

    // ---- join: folded weights ready before layer 1 ----
    cudaStreamWaitEvent(0, evJ, 0);

    for (int a = 1; a < 4; a++) {
        gemm_f16<1><<<gQKV, blk, SMEM1>>>(Ahp, nullptr, WcT + (a - 1) * WCS,
                                          Bcomb + (size_t)(a - 1) * QKV_N, nullptr,
                                          QKVh, nullptr, QKV_N, E_DIM, 0, 0, 0);

        const float* rba = rb + (size_t)a * RB_ONE;
        if ((a & 1) == 0) {
            attn_mma<<<dim3(H_DIM, B_DIM * T_DIM, 2), blk, ATTN_SMEM>>>(
                QKVh, QKVh + E_DIM, QKVh + 2 * E_DIM, Ahp, rba, QKV_N);
        } else {
            attn_mma_t<<<dim3(H_DIM, (B_DIM * N_DIM) / 8), blk, ATTN_T_SMEM>>>(
                QKVh, QKVh + E_DIM, QKVh + 2 * E_DIM, Ahp, rba, QKV_N);
        }
    }

    // ---- tail fork: ctx^T on s2 concurrent with score path on main ----
    cudaEventRecord(evA, 0);
    cudaStreamWaitEvent(s2, evA, 0);
    transp_h16<<<dim3(E_DIM / 32, MTOK_B / 32, B_DIM), tblk, 0, s2>>>(Ahp, CTh, MTOK_B, E_DIM);
    cudaEventRecord(evT, s2);

    // selection scores on ctx: SC = ctx_hi @ Bsel^T + Bias2
    gemm_f16<1><<<dim3(KSEL / 128, MTOK / 128), blk, SMEM1>>>(
        Ahp, nullptr, Bsel, Bias2, SCb, nullptr, nullptr, KSEL, E_DIM, 0, 0, 0);

    sel_softmax<<<dim3(B_DIM, KSEL / 32), blk>>>(SCb);

    transp_hilo<<<dim3(KSEL / 32, MTOK_B / 32, B_DIM), tblk>>>(SCb, SCTh, SCTl, MTOK_B, KSEL);

    // join ctx^T, then S1 = wts^T @ ctx  (mma split-K + fp32 atomics)
    cudaStreamWaitEvent(0, evT, 0);
    gemm_sel_mma<<<dim3(E_DIM / 128, KSEL / 128, B_DIM * SPLITK_SEL), blk, SMEM_SEL>>>(
        SCTh, SCTl, CTh, S1b);

    // SEL = S1 @ Wd3 + bd3  (tiny 2-seg GEMM)
    cvt_hilo<<<dim3((B_DIM * KSEL * E_DIM / 4 + 255) / 256), blk>>>(
        S1b, Ah2p, Al2p, B_DIM * KSEL * E_DIM / 4);
    gemm_f16<2><<<dim3(E_DIM / 128, (B_DIM * KSEL) / 128), blk, SMEM2>>>(
        Ah2p, Al2p, WdT3, bd + 3 * E_DIM, SELb, nullptr, nullptr, E_DIM, E_DIM, 0, 0, 0);

    int total = B_DIM * OUT_ROWS * E_DIM;
    pool_kernel<<<(total + 255) / 256, 256>>>(SELb, out);
}